// round 4
// baseline (speedup 1.0000x reference)
#include <cuda_runtime.h>
#include <cuda_bf16.h>
#include <mma.h>

using namespace nvcuda;

#define NN   32768
#define DD   128
#define BB   64
#define NPGC 512
#define EE   524288
#define KCL  5
#define H2D  256
#define CBN  512

typedef __nv_bfloat16 bf16;

// ---------------- scratch (device globals; no runtime allocation) ----------------
__device__ float g_h[NN*DD];
__device__ bf16  g_ahi[NN*DD],  g_alo[NN*DD];     // final-layer activation split (partitioner A)
__device__ float g_S[NN*KCL];
__device__ float g_cf[BB*KCL*DD];
__device__ float g_zq[BB*KCL*DD];
__device__ float g_res[BB*DD];
__device__ int   g_off[NN+1], g_srcl[EE];
__device__ bf16  g_w1hi[3*DD*H2D], g_w1lo[3*DD*H2D];
__device__ bf16  g_w2hi[3*H2D*DD], g_w2lo[3*H2D*DD];
__device__ bf16  g_pwhi[DD*128],   g_pwlo[DD*128];   // partitioner W1 padded 50->128
__device__ float g_pb1[128];

__device__ __forceinline__ void bsplit(float v, bf16& hi, bf16& lo) {
    hi = __float2bfloat16(v);
    lo = __float2bfloat16(v - __bfloat162float(hi));
}

// ---------------- per-graph CSR build (counting sort in smem) + zero g_res ----------------
__global__ void csr_kernel(const int* __restrict__ ei) {
    __shared__ int cnt[512];
    __shared__ int offs[512];
    int g = blockIdx.x, t = threadIdx.x;       // 64 blocks x 512 threads
    cnt[t] = 0;
    if (t < 128) g_res[g*128 + t] = 0.0f;
    __syncthreads();
    int ebase = g*8192;
    int nbase = g*512;
    #pragma unroll
    for (int i = 0; i < 16; i++) {
        int e = ebase + t + i*512;
        int d = ei[EE + e] - nbase;            // local dst (edges stay in-graph)
        atomicAdd(&cnt[d], 1);
    }
    __syncthreads();
    offs[t] = cnt[t];
    __syncthreads();
    for (int off = 1; off < 512; off <<= 1) {
        int v = (t >= off) ? offs[t-off] : 0;
        __syncthreads();
        offs[t] += v;
        __syncthreads();
    }
    int excl = offs[t] - cnt[t];
    g_off[nbase + t] = ebase + excl;
    if (g == BB-1 && t == 511) g_off[NN] = EE;
    cnt[t] = excl;                              // reuse as scatter cursor
    __syncthreads();
    #pragma unroll
    for (int i = 0; i < 16; i++) {
        int e = ebase + t + i*512;
        int d = ei[EE + e] - nbase;
        int p = atomicAdd(&cnt[d], 1);
        g_srcl[ebase + p] = ei[e];
    }
}

// ---------------- prep (weight splits) + embedding, merged ----------------
__global__ void prep_embed(const int* __restrict__ x, const float* __restrict__ emb,
                           const float* __restrict__ gW1, const float* __restrict__ gW2,
                           const float* __restrict__ pW1, const float* __restrict__ pb1) {
    int i = blockIdx.x*256 + threadIdx.x;
    if (i < NN*DD) { g_h[i] = emb[x[i >> 7]*DD + (i & 127)]; return; }
    i -= NN*DD;
    if (i < 3*DD*H2D) { bsplit(gW1[i], g_w1hi[i], g_w1lo[i]); return; }
    i -= 3*DD*H2D;
    if (i < 3*H2D*DD) { bsplit(gW2[i], g_w2hi[i], g_w2lo[i]); return; }
    i -= 3*H2D*DD;
    if (i < DD*128) {
        int rw = i >> 7, cl = i & 127;
        float v = (cl < 50) ? pW1[rw*50 + cl] : 0.0f;
        bsplit(v, g_pwhi[i], g_pwlo[i]);
        return;
    }
    i -= DD*128;
    if (i < 128) g_pb1[i] = (i < 50) ? pb1[i] : 0.0f;
}

// ---------------- fused GIN layer: gather + MLP(gemm1,gemm2) + BN, all in smem ----------------
// block: 512 threads, 128 nodes. smem: z region (2x128x136 bf16 = 69632 B) +
// W/hidden region (2x128x264 bf16 = 135168 B) = 204800 B.
#define LDZ 136
#define LDW 264
#define GIN_SMEM (2*128*LDZ*2 + 2*128*LDW*2)

__global__ __launch_bounds__(512, 1)
void ginlayer(const bf16* __restrict__ W1h, const bf16* __restrict__ W1l,
              const bf16* __restrict__ W2h, const bf16* __restrict__ W2l,
              const float* __restrict__ b1, const float* __restrict__ b2,
              const float* __restrict__ gamma, const float* __restrict__ beta,
              int last)
{
    extern __shared__ __align__(16) char smem[];
    bf16* sZh = (bf16*)smem;                   // z hi  (also W2-chunk hi later)
    bf16* sZl = sZh + 128*LDZ;                 // z lo  (also W2-chunk lo later)
    bf16* sWh = sZl + 128*LDZ;                 // W1 hi -> hidden hi
    bf16* sWl = sWh + 128*LDW;                 // W1 lo -> hidden lo
    float* scratch  = (float*)smem;            // f32 out staging (z region), pitch 132
    float* scratch2 = (float*)sWh;             // f32 out staging (W region), pitch 132

    int t = threadIdx.x, w = t >> 5, lane = t & 31;
    int wm = w & 3, wn = w >> 2;               // 4m x 4n warp grid
    int m0 = blockIdx.x*128;

    // ---- Phase A: stage W1 (128x256 hi/lo) + gather z ----
    #pragma unroll
    for (int i = 0; i < 8; i++) {
        int idx = t + i*512;                   // 4096 uint4 per array
        int r = idx >> 5, p = idx & 31;
        *(uint4*)(sWh + r*LDW + p*8) = *(const uint4*)(W1h + r*256 + p*8);
        *(uint4*)(sWl + r*LDW + p*8) = *(const uint4*)(W1l + r*256 + p*8);
    }
    {
        const float4* h4 = (const float4*)g_h;
        #pragma unroll
        for (int i = 0; i < 8; i++) {
            int r = w*8 + i;
            int node = m0 + r;
            float4 a = h4[(size_t)node*32 + lane];
            int e0 = g_off[node], e1 = g_off[node+1];
            for (int j = e0; j < e1; j++) {
                int s = g_srcl[j];
                float4 v = h4[(size_t)s*32 + lane];
                a.x += v.x; a.y += v.y; a.z += v.z; a.w += v.w;
            }
            __nv_bfloat162* ph = (__nv_bfloat162*)(sZh + r*LDZ);
            __nv_bfloat162* pl = (__nv_bfloat162*)(sZl + r*LDZ);
            bf16 h0,l0,h1,l1;
            bsplit(a.x, h0, l0); bsplit(a.y, h1, l1);
            ph[lane*2]   = __halves2bfloat162(h0, h1);
            pl[lane*2]   = __halves2bfloat162(l0, l1);
            bsplit(a.z, h0, l0); bsplit(a.w, h1, l1);
            ph[lane*2+1] = __halves2bfloat162(h0, h1);
            pl[lane*2+1] = __halves2bfloat162(l0, l1);
        }
    }
    __syncthreads();

    // ---- Phase B: gemm1  hidden[128x256] = z[128x128] @ W1[128x256], 3-split ----
    wmma::fragment<wmma::accumulator,16,16,16,float> acc1[2][4];
    #pragma unroll
    for (int i = 0; i < 2; i++)
        #pragma unroll
        for (int j = 0; j < 4; j++)
            wmma::fill_fragment(acc1[i][j], 0.0f);

    #pragma unroll
    for (int s = 0; s < 3; s++) {
        const bf16* Ap = (s == 2) ? sZl : sZh;
        const bf16* Bp = (s == 1) ? sWl : sWh;
        #pragma unroll
        for (int kb = 0; kb < 8; kb++) {
            wmma::fragment<wmma::matrix_a,16,16,16,bf16,wmma::row_major> af[2];
            wmma::fragment<wmma::matrix_b,16,16,16,bf16,wmma::row_major> bfr[4];
            #pragma unroll
            for (int i = 0; i < 2; i++)
                wmma::load_matrix_sync(af[i], Ap + (wm*32 + i*16)*LDZ + kb*16, LDZ);
            #pragma unroll
            for (int j = 0; j < 4; j++)
                wmma::load_matrix_sync(bfr[j], Bp + (kb*16)*LDW + wn*64 + j*16, LDW);
            #pragma unroll
            for (int i = 0; i < 2; i++)
                #pragma unroll
                for (int j = 0; j < 4; j++)
                    wmma::mma_sync(acc1[i][j], af[i], bfr[j], acc1[i][j]);
        }
    }

    // ---- Phase C: hidden epilogue (bias+relu+split), overwrite W1 region, 2 N-halves ----
    #pragma unroll
    for (int nh = 0; nh < 2; nh++) {
        __syncthreads();
        if ((wn >> 1) == nh) {
            #pragma unroll
            for (int i = 0; i < 2; i++)
                #pragma unroll
                for (int j = 0; j < 4; j++)
                    wmma::store_matrix_sync(scratch + (wm*32 + i*16)*132 + (wn & 1)*64 + j*16,
                                            acc1[i][j], 132, wmma::mem_row_major);
        }
        __syncthreads();
        #pragma unroll 4
        for (int it = 0; it < 32; it++) {
            int idx = t + it*512;
            int r = idx >> 7, c = idx & 127;
            int C = nh*128 + c;
            float v = fmaxf(scratch[r*132 + c] + __ldg(b1 + C), 0.0f);
            bf16 hi, lo; bsplit(v, hi, lo);
            sWh[r*LDW + C] = hi;
            sWl[r*LDW + C] = lo;
        }
    }

    // ---- Phase D: gemm2  out[128x128] = hidden[128x256] @ W2[256x128], 2 K-chunks ----
    wmma::fragment<wmma::accumulator,16,16,16,float> acc2[2][2];
    #pragma unroll
    for (int i = 0; i < 2; i++)
        #pragma unroll
        for (int j = 0; j < 2; j++)
            wmma::fill_fragment(acc2[i][j], 0.0f);

    #pragma unroll
    for (int c = 0; c < 2; c++) {
        __syncthreads();
        #pragma unroll
        for (int i = 0; i < 4; i++) {          // stage W2 chunk into z region
            int idx = t + i*512;               // 2048 uint4 per array
            int r = idx >> 4, p = idx & 15;
            *(uint4*)(sZh + r*LDZ + p*8) = *(const uint4*)(W2h + (size_t)(c*128 + r)*128 + p*8);
            *(uint4*)(sZl + r*LDZ + p*8) = *(const uint4*)(W2l + (size_t)(c*128 + r)*128 + p*8);
        }
        __syncthreads();
        #pragma unroll
        for (int s = 0; s < 3; s++) {
            const bf16* Ap = (s == 2) ? sWl : sWh;   // hidden
            const bf16* Bp = (s == 1) ? sZl : sZh;   // W2 chunk
            #pragma unroll
            for (int kb = 0; kb < 8; kb++) {
                wmma::fragment<wmma::matrix_a,16,16,16,bf16,wmma::row_major> af[2];
                wmma::fragment<wmma::matrix_b,16,16,16,bf16,wmma::row_major> bfr[2];
                #pragma unroll
                for (int i = 0; i < 2; i++)
                    wmma::load_matrix_sync(af[i], Ap + (wm*32 + i*16)*LDW + c*128 + kb*16, LDW);
                #pragma unroll
                for (int j = 0; j < 2; j++)
                    wmma::load_matrix_sync(bfr[j], Bp + (kb*16)*LDZ + wn*32 + j*16, LDZ);
                #pragma unroll
                for (int i = 0; i < 2; i++)
                    #pragma unroll
                    for (int j = 0; j < 2; j++)
                        wmma::mma_sync(acc2[i][j], af[i], bfr[j], acc2[i][j]);
            }
        }
    }
    __syncthreads();
    #pragma unroll
    for (int i = 0; i < 2; i++)
        #pragma unroll
        for (int j = 0; j < 2; j++)
            wmma::store_matrix_sync(scratch2 + (wm*32 + i*16)*132 + wn*32 + j*16,
                                    acc2[i][j], 132, wmma::mem_row_major);
    __syncthreads();

    // ---- Phase E: final epilogue (bias + BN [+relu]) -> g_h [+split, residue] ----
    const float BNS = 0.99999500003749971f;    // 1/sqrt(1+1e-5)
    int ccol = t & 127;
    float rsum = 0.0f;
    #pragma unroll 4
    for (int it = 0; it < 32; it++) {
        int idx = t + it*512;
        int r = idx >> 7;
        float v = scratch2[r*132 + ccol] + __ldg(b2 + ccol);
        v = v*(BNS*__ldg(gamma + ccol)) + __ldg(beta + ccol);
        if (!last) v = fmaxf(v, 0.0f);
        size_t gi = (size_t)(m0 + r)*128 + ccol;
        g_h[gi] = v;
        if (last) {
            bf16 hi, lo; bsplit(v, hi, lo);
            g_ahi[gi] = hi;
            g_alo[gi] = lo;
            rsum += v;
        }
    }
    if (last)
        atomicAdd(&g_res[(m0 >> 9)*128 + ccol], rsum);
}

// ---------------- partitioner GEMM (128x128, K=128, 3-split) + fused W2 GEMV + softmax ----------------
#define SM_LDA 136
#define SM_LDO 132
#define SMEM_BYTES (4*128*SM_LDA*2)

__global__ void part_gemm(const bf16* __restrict__ Ahi, const bf16* __restrict__ Alo,
                          const bf16* __restrict__ Bhi, const bf16* __restrict__ Blo,
                          const float* __restrict__ bias,
                          const float* __restrict__ pW2, const float* __restrict__ pb2)
{
    extern __shared__ __align__(16) char smem[];
    bf16* sAh = (bf16*)smem;
    bf16* sAl = sAh + 128*SM_LDA;
    bf16* sBh = sAl + 128*SM_LDA;
    bf16* sBl = sBh + 128*SM_LDA;
    float* sO  = (float*)smem;
    float* w2s = (float*)(smem + 128*SM_LDO*4);

    int t = threadIdx.x, w = t >> 5;
    int wm = w & 3, wn = w >> 2;
    int m0 = blockIdx.x*128;

    wmma::fragment<wmma::accumulator,16,16,16,float> acc[2][4];
    #pragma unroll
    for (int i = 0; i < 2; i++)
        #pragma unroll
        for (int j = 0; j < 4; j++)
            wmma::fill_fragment(acc[i][j], 0.0f);

    #pragma unroll
    for (int i = 0; i < 8; i++) {
        int idx = t + i*256;
        int r = idx >> 4, p = idx & 15;
        *(uint4*)(sAh + r*SM_LDA + p*8) = *(const uint4*)(Ahi + (size_t)(m0 + r)*128 + p*8);
        *(uint4*)(sAl + r*SM_LDA + p*8) = *(const uint4*)(Alo + (size_t)(m0 + r)*128 + p*8);
        *(uint4*)(sBh + r*SM_LDA + p*8) = *(const uint4*)(Bhi + (size_t)r*128 + p*8);
        *(uint4*)(sBl + r*SM_LDA + p*8) = *(const uint4*)(Blo + (size_t)r*128 + p*8);
    }
    __syncthreads();

    #pragma unroll
    for (int s = 0; s < 3; s++) {
        const bf16* Ap = (s == 2) ? sAl : sAh;
        const bf16* Bp = (s == 1) ? sBl : sBh;
        #pragma unroll
        for (int kb = 0; kb < 8; kb++) {
            wmma::fragment<wmma::matrix_a,16,16,16,bf16,wmma::row_major> af[2];
            wmma::fragment<wmma::matrix_b,16,16,16,bf16,wmma::row_major> bfr[4];
            #pragma unroll
            for (int i = 0; i < 2; i++)
                wmma::load_matrix_sync(af[i], Ap + (wm*32 + i*16)*SM_LDA + kb*16, SM_LDA);
            #pragma unroll
            for (int j = 0; j < 4; j++)
                wmma::load_matrix_sync(bfr[j], Bp + (kb*16)*SM_LDA + wn*32 + j*16, SM_LDA);
            #pragma unroll
            for (int i = 0; i < 2; i++)
                #pragma unroll
                for (int j = 0; j < 4; j++)
                    wmma::mma_sync(acc[i][j], af[i], bfr[j], acc[i][j]);
        }
    }
    __syncthreads();
    #pragma unroll
    for (int i = 0; i < 2; i++)
        #pragma unroll
        for (int j = 0; j < 4; j++)
            wmma::store_matrix_sync(sO + (wm*32 + i*16)*SM_LDO + wn*32 + j*16, acc[i][j],
                                    SM_LDO, wmma::mem_row_major);
    if (t < 255) w2s[t] = (t < 250) ? pW2[t] : pb2[t - 250];
    __syncthreads();

    if (t < 128) {
        float cr[50];
        #pragma unroll
        for (int j = 0; j < 50; j++)
            cr[j] = fmaxf(sO[t*SM_LDO + j] + bias[j], 0.0f);
        float l[5];
        #pragma unroll
        for (int k = 0; k < 5; k++) {
            float a = w2s[250 + k];
            #pragma unroll
            for (int j = 0; j < 50; j++) a += cr[j]*w2s[j*5 + k];
            l[k] = a;
        }
        float m = l[0];
        #pragma unroll
        for (int k = 1; k < 5; k++) m = fmaxf(m, l[k]);
        float e[5], s = 0.0f;
        #pragma unroll
        for (int k = 0; k < 5; k++) { e[k] = expf(l[k] - m); s += e[k]; }
        float inv = 1.0f/s;
        #pragma unroll
        for (int k = 0; k < 5; k++) g_S[(size_t)(m0 + t)*5 + k] = e[k]*inv;
    }
}

// ---------------- soft-cluster pooling ----------------
__global__ void cf_kernel() {
    int g = blockIdx.x, t = threadIdx.x;     // 640 threads
    __shared__ float sh[64*128];
    __shared__ float sS[64*5];
    int k = t >> 7, c = t & 127;
    float acc = 0.0f, ss = 0.0f;
    for (int ch = 0; ch < 8; ch++) {
        int nb = ch*64;
        const float* hb = g_h + ((size_t)g*NPGC + nb)*DD;
        for (int i = t; i < 64*128; i += 640) sh[i] = hb[i];
        const float* sb = g_S + ((size_t)g*NPGC + nb)*5;
        for (int i = t; i < 320; i += 640) sS[i] = sb[i];
        __syncthreads();
        for (int n2 = 0; n2 < 64; n2++) {
            float s = sS[n2*5 + k];
            acc += s*sh[n2*128 + c];
            ss  += s;
        }
        __syncthreads();
    }
    g_cf[((size_t)g*5 + k)*128 + c] = acc/(ss + 1e-6f);
}

// ---------------- VQ nearest codebook ----------------
__global__ void vq_kernel(const float* __restrict__ codebook) {
    int row = blockIdx.x;
    int t = threadIdx.x, w = t >> 5, lane = t & 31;
    __shared__ __align__(16) float f[128];
    __shared__ float wbest[4];
    __shared__ int   widx[4];
    __shared__ int   bestidx;
    f[t] = g_cf[(size_t)row*128 + t];
    __syncthreads();
    float4 fv = ((const float4*)f)[lane];
    float best = 3.4e38f;
    int bi = 0;
    for (int rr = w; rr < CBN; rr += 4) {
        const float4* cb4 = (const float4*)(codebook + (size_t)rr*128);
        float4 cv = cb4[lane];
        float dx = cv.x - fv.x, dy = cv.y - fv.y, dz = cv.z - fv.z, dw = cv.w - fv.w;
        float d = dx*dx + dy*dy + dz*dz + dw*dw;
        #pragma unroll
        for (int o = 16; o; o >>= 1) d += __shfl_xor_sync(0xffffffff, d, o);
        if (d < best) { best = d; bi = rr; }
    }
    if (lane == 0) { wbest[w] = best; widx[w] = bi; }
    __syncthreads();
    if (t == 0) {
        float bb = wbest[0]; int ii = widx[0];
        for (int j = 1; j < 4; j++)
            if (wbest[j] < bb || (wbest[j] == bb && widx[j] < ii)) { bb = wbest[j]; ii = widx[j]; }
        bestidx = ii;
    }
    __syncthreads();
    g_zq[(size_t)row*128 + t] = codebook[(size_t)bestidx*128 + t];
}

// ---------------- fused attention + gate + classifier (per-graph) ----------------
__global__ void tail_kernel(const float* __restrict__ Wq, const float* __restrict__ Wk,
                            const float* __restrict__ Wv, const float* __restrict__ Wo,
                            const float* __restrict__ gW1, const float* __restrict__ gb1,
                            const float* __restrict__ gW2, const float* __restrict__ gb2,
                            const float* __restrict__ cW1, const float* __restrict__ cb1,
                            const float* __restrict__ cW2, const float* __restrict__ cb2,
                            const float* __restrict__ cW3, const float* __restrict__ cb3,
                            float* __restrict__ out)
{
    int g = blockIdx.x, t = threadIdx.x;     // 128 threads
    __shared__ float r[128], zq5[5*128], qv[128], kk[5*128], vv[5*128];
    __shared__ float sc[20], aw[20], attv[128], attn[128], g1[64], fused[128];
    __shared__ float z1[512], z2[256];

    r[t] = g_res[g*128 + t]*(1.0f/NPGC);
    #pragma unroll
    for (int j = 0; j < 5; j++) zq5[j*128 + t] = g_zq[((size_t)g*5 + j)*128 + t];
    __syncthreads();

    {
        float a = 0.0f;
        for (int k2 = 0; k2 < 128; k2++) a += r[k2]*Wq[k2*128 + t];
        qv[t] = a;
    }
    {
        float a5[5] = {0,0,0,0,0};
        for (int k2 = 0; k2 < 128; k2++) {
            float wv2 = Wk[k2*128 + t];
            #pragma unroll
            for (int j = 0; j < 5; j++) a5[j] += zq5[j*128 + k2]*wv2;
        }
        #pragma unroll
        for (int j = 0; j < 5; j++) kk[j*128 + t] = a5[j];
    }
    {
        float a5[5] = {0,0,0,0,0};
        for (int k2 = 0; k2 < 128; k2++) {
            float wv2 = Wv[k2*128 + t];
            #pragma unroll
            for (int j = 0; j < 5; j++) a5[j] += zq5[j*128 + k2]*wv2;
        }
        #pragma unroll
        for (int j = 0; j < 5; j++) vv[j*128 + t] = a5[j];
    }
    __syncthreads();

    if (t < 20) {
        int hh = t/5, j = t%5;
        float s = 0.0f;
        for (int d2 = 0; d2 < 32; d2++) s += qv[hh*32 + d2]*kk[j*128 + hh*32 + d2];
        sc[t] = s*0.17677669529663687f;
    }
    __syncthreads();
    if (t < 4) {
        float m = -1e30f;
        #pragma unroll
        for (int j = 0; j < 5; j++) m = fmaxf(m, sc[t*5 + j]);
        float e[5], s = 0.0f;
        #pragma unroll
        for (int j = 0; j < 5; j++) { e[j] = expf(sc[t*5 + j] - m); s += e[j]; }
        float inv = 1.0f/s;
        #pragma unroll
        for (int j = 0; j < 5; j++) aw[t*5 + j] = e[j]*inv;
    }
    __syncthreads();
    {
        int hh = t >> 5;
        float a = 0.0f;
        #pragma unroll
        for (int j = 0; j < 5; j++) a += aw[hh*5 + j]*vv[j*128 + t];
        attv[t] = a;
    }
    __syncthreads();
    {
        float a = 0.0f;
        for (int k2 = 0; k2 < 128; k2++) a += attv[k2]*Wo[k2*128 + t];
        attn[t] = a;
    }
    __syncthreads();
    if (t < 64) {
        float a = gb1[t];
        for (int k2 = 0; k2 < 128; k2++) a += r[k2]*gW1[k2*64 + t];
        for (int k2 = 0; k2 < 128; k2++) a += attn[k2]*gW1[(128 + k2)*64 + t];
        g1[t] = fmaxf(a, 0.0f);
    }
    __syncthreads();
    {
        float a = gb2[t];
        for (int k2 = 0; k2 < 64; k2++) a += g1[k2]*gW2[k2*128 + t];
        float gg = 1.0f/(1.0f + expf(-a));
        fused[t] = gg*r[t] + (1.0f - gg)*attn[t];
    }
    __syncthreads();
    for (int o = t; o < 512; o += 128) {
        float a = cb1[o];
        for (int k2 = 0; k2 < 128; k2++) a += fused[k2]*cW1[k2*512 + o];
        z1[o] = fmaxf(a, 0.0f);
    }
    __syncthreads();
    for (int o = t; o < 256; o += 128) {
        float a = cb2[o];
        for (int k2 = 0; k2 < 512; k2++) a += z1[k2]*cW2[k2*256 + o];
        z2[o] = fmaxf(a, 0.0f);
    }
    __syncthreads();
    if (t < 2) {
        float a = cb3[t];
        for (int k2 = 0; k2 < 256; k2++) a += z2[k2]*cW3[k2*2 + t];
        out[g*2 + t] = a;
    }
}

// ---------------- host launch ----------------
extern "C" void kernel_launch(void* const* d_in, const int* in_sizes, int n_in,
                              void* d_out, int out_size) {
    (void)in_sizes; (void)n_in; (void)out_size;
    const int*   x     = (const int*)d_in[0];
    const int*   ei    = (const int*)d_in[1];
    const float* emb   = (const float*)d_in[3];
    const float* gW1   = (const float*)d_in[4];
    const float* gb1v  = (const float*)d_in[5];
    const float* gW2   = (const float*)d_in[6];
    const float* gb2v  = (const float*)d_in[7];
    const float* bng   = (const float*)d_in[8];
    const float* bnb   = (const float*)d_in[9];
    const float* pW1   = (const float*)d_in[10];
    const float* pb1   = (const float*)d_in[11];
    const float* pW2   = (const float*)d_in[12];
    const float* pb2   = (const float*)d_in[13];
    const float* Wq    = (const float*)d_in[14];
    const float* Wk    = (const float*)d_in[15];
    const float* Wv    = (const float*)d_in[16];
    const float* Wo    = (const float*)d_in[17];
    const float* gateW1= (const float*)d_in[18];
    const float* gateb1= (const float*)d_in[19];
    const float* gateW2= (const float*)d_in[20];
    const float* gateb2= (const float*)d_in[21];
    const float* cbk   = (const float*)d_in[22];
    const float* cW1   = (const float*)d_in[23];
    const float* cb1   = (const float*)d_in[24];
    const float* cW2   = (const float*)d_in[25];
    const float* cb2   = (const float*)d_in[26];
    const float* cW3   = (const float*)d_in[27];
    const float* cb3   = (const float*)d_in[28];
    float* out = (float*)d_out;

    bf16 *ahi, *alo, *w1hi, *w1lo, *w2hi, *w2lo, *pwhi, *pwlo;
    float *ppb1;
    cudaGetSymbolAddress((void**)&ahi,  g_ahi);
    cudaGetSymbolAddress((void**)&alo,  g_alo);
    cudaGetSymbolAddress((void**)&w1hi, g_w1hi);
    cudaGetSymbolAddress((void**)&w1lo, g_w1lo);
    cudaGetSymbolAddress((void**)&w2hi, g_w2hi);
    cudaGetSymbolAddress((void**)&w2lo, g_w2lo);
    cudaGetSymbolAddress((void**)&pwhi, g_pwhi);
    cudaGetSymbolAddress((void**)&pwlo, g_pwlo);
    cudaGetSymbolAddress((void**)&ppb1, g_pb1);

    cudaFuncSetAttribute(ginlayer,  cudaFuncAttributeMaxDynamicSharedMemorySize, GIN_SMEM);
    cudaFuncSetAttribute(part_gemm, cudaFuncAttributeMaxDynamicSharedMemorySize, SMEM_BYTES);

    csr_kernel<<<BB, 512>>>(ei);
    {
        int tot = NN*DD + 3*DD*H2D + 3*H2D*DD + DD*128 + 128;
        prep_embed<<<(tot + 255)/256, 256>>>(x, emb, gW1, gW2, pW1, pb1);
    }

    for (int l = 0; l < 3; l++) {
        ginlayer<<<NN/128, 512, GIN_SMEM>>>(
            w1hi + (size_t)l*DD*H2D, w1lo + (size_t)l*DD*H2D,
            w2hi + (size_t)l*H2D*DD, w2lo + (size_t)l*H2D*DD,
            gb1v + l*H2D, gb2v + l*DD, bng + l*DD, bnb + l*DD,
            (l == 2) ? 1 : 0);
    }

    part_gemm<<<NN/128, 256, SMEM_BYTES>>>(ahi, alo, pwhi, pwlo, ppb1, pW2, pb2);

    cf_kernel  <<<BB, 640>>>();
    vq_kernel  <<<BB*KCL, 128>>>(cbk);
    tail_kernel<<<BB, 128>>>(Wq, Wk, Wv, Wo, gateW1, gateb1, gateW2, gateb2,
                             cW1, cb1, cW2, cb2, cW3, cb3, out);
}

// round 5
// speedup vs baseline: 1.0023x; 1.0023x over previous
#include <cuda_runtime.h>
#include <cuda_bf16.h>
#include <mma.h>

using namespace nvcuda;

#define NN   32768
#define DD   128
#define BB   64
#define NPGC 512
#define EE   524288
#define KCL  5
#define H2D  256
#define CBN  512

typedef __nv_bfloat16 bf16;

// ---------------- scratch (device globals; no runtime allocation) ----------------
__device__ float g_h[NN*DD];
__device__ bf16  g_ahi[NN*DD],  g_alo[NN*DD];     // final-layer activation split (partitioner A)
__device__ float g_S[NN*KCL];
__device__ float g_cf[BB*KCL*DD];
__device__ float g_zq[BB*KCL*DD];
__device__ float g_res[BB*DD];
__device__ int   g_off[NN+1], g_srcl[EE];
__device__ bf16  g_w1hi[3*DD*H2D], g_w1lo[3*DD*H2D];
__device__ bf16  g_w2hi[3*H2D*DD], g_w2lo[3*H2D*DD];
__device__ bf16  g_pwhi[DD*128],   g_pwlo[DD*128];   // partitioner W1 padded 50->128
__device__ float g_pb1[128];

__device__ __forceinline__ void bsplit(float v, bf16& hi, bf16& lo) {
    hi = __float2bfloat16(v);
    lo = __float2bfloat16(v - __bfloat162float(hi));
}

// ---------------- per-graph CSR build (counting sort in smem) + zero g_res ----------------
__global__ void csr_kernel(const int* __restrict__ ei) {
    __shared__ int cnt[512];
    __shared__ int offs[512];
    int g = blockIdx.x, t = threadIdx.x;       // 64 blocks x 512 threads
    cnt[t] = 0;
    if (t < 128) g_res[g*128 + t] = 0.0f;
    __syncthreads();
    int ebase = g*8192;
    int nbase = g*512;
    #pragma unroll
    for (int i = 0; i < 16; i++) {
        int e = ebase + t + i*512;
        int d = ei[EE + e] - nbase;            // local dst (edges stay in-graph)
        atomicAdd(&cnt[d], 1);
    }
    __syncthreads();
    offs[t] = cnt[t];
    __syncthreads();
    for (int off = 1; off < 512; off <<= 1) {
        int v = (t >= off) ? offs[t-off] : 0;
        __syncthreads();
        offs[t] += v;
        __syncthreads();
    }
    int excl = offs[t] - cnt[t];
    g_off[nbase + t] = ebase + excl;
    if (g == BB-1 && t == 511) g_off[NN] = EE;
    cnt[t] = excl;                              // reuse as scatter cursor
    __syncthreads();
    #pragma unroll
    for (int i = 0; i < 16; i++) {
        int e = ebase + t + i*512;
        int d = ei[EE + e] - nbase;
        int p = atomicAdd(&cnt[d], 1);
        g_srcl[ebase + p] = ei[e];
    }
}

// ---------------- prep (weight splits) + embedding, merged ----------------
__global__ void prep_embed(const int* __restrict__ x, const float* __restrict__ emb,
                           const float* __restrict__ gW1, const float* __restrict__ gW2,
                           const float* __restrict__ pW1, const float* __restrict__ pb1) {
    int i = blockIdx.x*256 + threadIdx.x;
    if (i < NN*DD) { g_h[i] = emb[x[i >> 7]*DD + (i & 127)]; return; }
    i -= NN*DD;
    if (i < 3*DD*H2D) { bsplit(gW1[i], g_w1hi[i], g_w1lo[i]); return; }
    i -= 3*DD*H2D;
    if (i < 3*H2D*DD) { bsplit(gW2[i], g_w2hi[i], g_w2lo[i]); return; }
    i -= 3*H2D*DD;
    if (i < DD*128) {
        int rw = i >> 7, cl = i & 127;
        float v = (cl < 50) ? pW1[rw*50 + cl] : 0.0f;
        bsplit(v, g_pwhi[i], g_pwlo[i]);
        return;
    }
    i -= DD*128;
    if (i < 128) g_pb1[i] = (i < 50) ? pb1[i] : 0.0f;
}

// ---------------- fused GIN layer: gather + MLP(gemm1,gemm2) + BN, all in smem ----------------
// block: 512 threads, 128 nodes. smem: z region (2x128x136 bf16 = 69632 B) +
// W/hidden region (2x128x264 bf16 = 135168 B) = 204800 B.
#define LDZ 136
#define LDW 264
#define GIN_SMEM (2*128*LDZ*2 + 2*128*LDW*2)

__global__ __launch_bounds__(512, 1)
void ginlayer(const bf16* __restrict__ W1h, const bf16* __restrict__ W1l,
              const bf16* __restrict__ W2h, const bf16* __restrict__ W2l,
              const float* __restrict__ b1, const float* __restrict__ b2,
              const float* __restrict__ gamma, const float* __restrict__ beta,
              int last)
{
    extern __shared__ __align__(16) char smem[];
    bf16* sZh = (bf16*)smem;                   // z hi  (also W2-chunk hi later)
    bf16* sZl = sZh + 128*LDZ;                 // z lo  (also W2-chunk lo later)
    bf16* sWh = sZl + 128*LDZ;                 // W1 hi -> hidden hi
    bf16* sWl = sWh + 128*LDW;                 // W1 lo -> hidden lo
    float* scratch  = (float*)smem;            // f32 out staging (z region), pitch 132
    float* scratch2 = (float*)sWh;             // f32 out staging (W region), pitch 132

    int t = threadIdx.x, w = t >> 5, lane = t & 31;
    int wm = w & 3, wn = w >> 2;               // 4m x 4n warp grid
    int m0 = blockIdx.x*128;

    // ---- Phase A: stage W1 (128x256 hi/lo) + gather z (MLP-unrolled) ----
    #pragma unroll
    for (int i = 0; i < 8; i++) {
        int idx = t + i*512;                   // 4096 uint4 per array
        int r = idx >> 5, p = idx & 31;
        *(uint4*)(sWh + r*LDW + p*8) = *(const uint4*)(W1h + r*256 + p*8);
        *(uint4*)(sWl + r*LDW + p*8) = *(const uint4*)(W1l + r*256 + p*8);
    }
    {
        const float4* __restrict__ h4 = (const float4*)g_h;
        #pragma unroll
        for (int i = 0; i < 8; i++) {
            int r = w*8 + i;
            int node = m0 + r;
            float4 a = h4[(size_t)node*32 + lane];
            int e0 = g_off[node], e1 = g_off[node+1];
            int j = e0;
            // batch 8 independent index loads, then 8 independent row loads (MLP=8)
            for (; j + 8 <= e1; j += 8) {
                int s0 = g_srcl[j+0], s1 = g_srcl[j+1], s2 = g_srcl[j+2], s3 = g_srcl[j+3];
                int s4 = g_srcl[j+4], s5 = g_srcl[j+5], s6 = g_srcl[j+6], s7 = g_srcl[j+7];
                float4 v0 = h4[(size_t)s0*32 + lane];
                float4 v1 = h4[(size_t)s1*32 + lane];
                float4 v2 = h4[(size_t)s2*32 + lane];
                float4 v3 = h4[(size_t)s3*32 + lane];
                float4 v4 = h4[(size_t)s4*32 + lane];
                float4 v5 = h4[(size_t)s5*32 + lane];
                float4 v6 = h4[(size_t)s6*32 + lane];
                float4 v7 = h4[(size_t)s7*32 + lane];
                a.x += ((v0.x + v1.x) + (v2.x + v3.x)) + ((v4.x + v5.x) + (v6.x + v7.x));
                a.y += ((v0.y + v1.y) + (v2.y + v3.y)) + ((v4.y + v5.y) + (v6.y + v7.y));
                a.z += ((v0.z + v1.z) + (v2.z + v3.z)) + ((v4.z + v5.z) + (v6.z + v7.z));
                a.w += ((v0.w + v1.w) + (v2.w + v3.w)) + ((v4.w + v5.w) + (v6.w + v7.w));
            }
            if (j + 4 <= e1) {
                int s0 = g_srcl[j+0], s1 = g_srcl[j+1], s2 = g_srcl[j+2], s3 = g_srcl[j+3];
                float4 v0 = h4[(size_t)s0*32 + lane];
                float4 v1 = h4[(size_t)s1*32 + lane];
                float4 v2 = h4[(size_t)s2*32 + lane];
                float4 v3 = h4[(size_t)s3*32 + lane];
                a.x += (v0.x + v1.x) + (v2.x + v3.x);
                a.y += (v0.y + v1.y) + (v2.y + v3.y);
                a.z += (v0.z + v1.z) + (v2.z + v3.z);
                a.w += (v0.w + v1.w) + (v2.w + v3.w);
                j += 4;
            }
            for (; j < e1; j++) {
                int s = g_srcl[j];
                float4 v = h4[(size_t)s*32 + lane];
                a.x += v.x; a.y += v.y; a.z += v.z; a.w += v.w;
            }
            __nv_bfloat162* ph = (__nv_bfloat162*)(sZh + r*LDZ);
            __nv_bfloat162* pl = (__nv_bfloat162*)(sZl + r*LDZ);
            bf16 h0,l0,h1,l1;
            bsplit(a.x, h0, l0); bsplit(a.y, h1, l1);
            ph[lane*2]   = __halves2bfloat162(h0, h1);
            pl[lane*2]   = __halves2bfloat162(l0, l1);
            bsplit(a.z, h0, l0); bsplit(a.w, h1, l1);
            ph[lane*2+1] = __halves2bfloat162(h0, h1);
            pl[lane*2+1] = __halves2bfloat162(l0, l1);
        }
    }
    __syncthreads();

    // ---- Phase B: gemm1  hidden[128x256] = z[128x128] @ W1[128x256], 3-split ----
    wmma::fragment<wmma::accumulator,16,16,16,float> acc1[2][4];
    #pragma unroll
    for (int i = 0; i < 2; i++)
        #pragma unroll
        for (int j = 0; j < 4; j++)
            wmma::fill_fragment(acc1[i][j], 0.0f);

    #pragma unroll
    for (int s = 0; s < 3; s++) {
        const bf16* Ap = (s == 2) ? sZl : sZh;
        const bf16* Bp = (s == 1) ? sWl : sWh;
        #pragma unroll
        for (int kb = 0; kb < 8; kb++) {
            wmma::fragment<wmma::matrix_a,16,16,16,bf16,wmma::row_major> af[2];
            wmma::fragment<wmma::matrix_b,16,16,16,bf16,wmma::row_major> bfr[4];
            #pragma unroll
            for (int i = 0; i < 2; i++)
                wmma::load_matrix_sync(af[i], Ap + (wm*32 + i*16)*LDZ + kb*16, LDZ);
            #pragma unroll
            for (int j = 0; j < 4; j++)
                wmma::load_matrix_sync(bfr[j], Bp + (kb*16)*LDW + wn*64 + j*16, LDW);
            #pragma unroll
            for (int i = 0; i < 2; i++)
                #pragma unroll
                for (int j = 0; j < 4; j++)
                    wmma::mma_sync(acc1[i][j], af[i], bfr[j], acc1[i][j]);
        }
    }

    // ---- Phase C: hidden epilogue (bias+relu+split), overwrite W1 region, 2 N-halves ----
    #pragma unroll
    for (int nh = 0; nh < 2; nh++) {
        __syncthreads();
        if ((wn >> 1) == nh) {
            #pragma unroll
            for (int i = 0; i < 2; i++)
                #pragma unroll
                for (int j = 0; j < 4; j++)
                    wmma::store_matrix_sync(scratch + (wm*32 + i*16)*132 + (wn & 1)*64 + j*16,
                                            acc1[i][j], 132, wmma::mem_row_major);
        }
        __syncthreads();
        #pragma unroll 4
        for (int it = 0; it < 32; it++) {
            int idx = t + it*512;
            int r = idx >> 7, c = idx & 127;
            int C = nh*128 + c;
            float v = fmaxf(scratch[r*132 + c] + __ldg(b1 + C), 0.0f);
            bf16 hi, lo; bsplit(v, hi, lo);
            sWh[r*LDW + C] = hi;
            sWl[r*LDW + C] = lo;
        }
    }

    // ---- Phase D: gemm2  out[128x128] = hidden[128x256] @ W2[256x128], 2 K-chunks ----
    wmma::fragment<wmma::accumulator,16,16,16,float> acc2[2][2];
    #pragma unroll
    for (int i = 0; i < 2; i++)
        #pragma unroll
        for (int j = 0; j < 2; j++)
            wmma::fill_fragment(acc2[i][j], 0.0f);

    #pragma unroll
    for (int c = 0; c < 2; c++) {
        __syncthreads();
        #pragma unroll
        for (int i = 0; i < 4; i++) {          // stage W2 chunk into z region
            int idx = t + i*512;               // 2048 uint4 per array
            int r = idx >> 4, p = idx & 15;
            *(uint4*)(sZh + r*LDZ + p*8) = *(const uint4*)(W2h + (size_t)(c*128 + r)*128 + p*8);
            *(uint4*)(sZl + r*LDZ + p*8) = *(const uint4*)(W2l + (size_t)(c*128 + r)*128 + p*8);
        }
        __syncthreads();
        #pragma unroll
        for (int s = 0; s < 3; s++) {
            const bf16* Ap = (s == 2) ? sWl : sWh;   // hidden
            const bf16* Bp = (s == 1) ? sZl : sZh;   // W2 chunk
            #pragma unroll
            for (int kb = 0; kb < 8; kb++) {
                wmma::fragment<wmma::matrix_a,16,16,16,bf16,wmma::row_major> af[2];
                wmma::fragment<wmma::matrix_b,16,16,16,bf16,wmma::row_major> bfr[2];
                #pragma unroll
                for (int i = 0; i < 2; i++)
                    wmma::load_matrix_sync(af[i], Ap + (wm*32 + i*16)*LDW + c*128 + kb*16, LDW);
                #pragma unroll
                for (int j = 0; j < 2; j++)
                    wmma::load_matrix_sync(bfr[j], Bp + (kb*16)*LDZ + wn*32 + j*16, LDZ);
                #pragma unroll
                for (int i = 0; i < 2; i++)
                    #pragma unroll
                    for (int j = 0; j < 2; j++)
                        wmma::mma_sync(acc2[i][j], af[i], bfr[j], acc2[i][j]);
            }
        }
    }
    __syncthreads();
    #pragma unroll
    for (int i = 0; i < 2; i++)
        #pragma unroll
        for (int j = 0; j < 2; j++)
            wmma::store_matrix_sync(scratch2 + (wm*32 + i*16)*132 + wn*32 + j*16,
                                    acc2[i][j], 132, wmma::mem_row_major);
    __syncthreads();

    // ---- Phase E: final epilogue (bias + BN [+relu]) -> g_h [+split, residue] ----
    const float BNS = 0.99999500003749971f;    // 1/sqrt(1+1e-5)
    int ccol = t & 127;
    float rsum = 0.0f;
    #pragma unroll 4
    for (int it = 0; it < 32; it++) {
        int idx = t + it*512;
        int r = idx >> 7;
        float v = scratch2[r*132 + ccol] + __ldg(b2 + ccol);
        v = v*(BNS*__ldg(gamma + ccol)) + __ldg(beta + ccol);
        if (!last) v = fmaxf(v, 0.0f);
        size_t gi = (size_t)(m0 + r)*128 + ccol;
        g_h[gi] = v;
        if (last) {
            bf16 hi, lo; bsplit(v, hi, lo);
            g_ahi[gi] = hi;
            g_alo[gi] = lo;
            rsum += v;
        }
    }
    if (last)
        atomicAdd(&g_res[(m0 >> 9)*128 + ccol], rsum);
}

// ---------------- partitioner GEMM (128x128, K=128, 3-split) + fused W2 GEMV + softmax ----------------
#define SM_LDA 136
#define SM_LDO 132
#define SMEM_BYTES (4*128*SM_LDA*2)

__global__ void part_gemm(const bf16* __restrict__ Ahi, const bf16* __restrict__ Alo,
                          const bf16* __restrict__ Bhi, const bf16* __restrict__ Blo,
                          const float* __restrict__ bias,
                          const float* __restrict__ pW2, const float* __restrict__ pb2)
{
    extern __shared__ __align__(16) char smem[];
    bf16* sAh = (bf16*)smem;
    bf16* sAl = sAh + 128*SM_LDA;
    bf16* sBh = sAl + 128*SM_LDA;
    bf16* sBl = sBh + 128*SM_LDA;
    float* sO  = (float*)smem;
    float* w2s = (float*)(smem + 128*SM_LDO*4);

    int t = threadIdx.x, w = t >> 5;
    int wm = w & 3, wn = w >> 2;
    int m0 = blockIdx.x*128;

    wmma::fragment<wmma::accumulator,16,16,16,float> acc[2][4];
    #pragma unroll
    for (int i = 0; i < 2; i++)
        #pragma unroll
        for (int j = 0; j < 4; j++)
            wmma::fill_fragment(acc[i][j], 0.0f);

    #pragma unroll
    for (int i = 0; i < 8; i++) {
        int idx = t + i*256;
        int r = idx >> 4, p = idx & 15;
        *(uint4*)(sAh + r*SM_LDA + p*8) = *(const uint4*)(Ahi + (size_t)(m0 + r)*128 + p*8);
        *(uint4*)(sAl + r*SM_LDA + p*8) = *(const uint4*)(Alo + (size_t)(m0 + r)*128 + p*8);
        *(uint4*)(sBh + r*SM_LDA + p*8) = *(const uint4*)(Bhi + (size_t)r*128 + p*8);
        *(uint4*)(sBl + r*SM_LDA + p*8) = *(const uint4*)(Blo + (size_t)r*128 + p*8);
    }
    __syncthreads();

    #pragma unroll
    for (int s = 0; s < 3; s++) {
        const bf16* Ap = (s == 2) ? sAl : sAh;
        const bf16* Bp = (s == 1) ? sBl : sBh;
        #pragma unroll
        for (int kb = 0; kb < 8; kb++) {
            wmma::fragment<wmma::matrix_a,16,16,16,bf16,wmma::row_major> af[2];
            wmma::fragment<wmma::matrix_b,16,16,16,bf16,wmma::row_major> bfr[4];
            #pragma unroll
            for (int i = 0; i < 2; i++)
                wmma::load_matrix_sync(af[i], Ap + (wm*32 + i*16)*SM_LDA + kb*16, SM_LDA);
            #pragma unroll
            for (int j = 0; j < 4; j++)
                wmma::load_matrix_sync(bfr[j], Bp + (kb*16)*SM_LDA + wn*32 + j*16, SM_LDA);
            #pragma unroll
            for (int i = 0; i < 2; i++)
                #pragma unroll
                for (int j = 0; j < 4; j++)
                    wmma::mma_sync(acc[i][j], af[i], bfr[j], acc[i][j]);
        }
    }
    __syncthreads();
    #pragma unroll
    for (int i = 0; i < 2; i++)
        #pragma unroll
        for (int j = 0; j < 4; j++)
            wmma::store_matrix_sync(sO + (wm*32 + i*16)*SM_LDO + wn*32 + j*16, acc[i][j],
                                    SM_LDO, wmma::mem_row_major);
    if (t < 255) w2s[t] = (t < 250) ? pW2[t] : pb2[t - 250];
    __syncthreads();

    if (t < 128) {
        float cr[50];
        #pragma unroll
        for (int j = 0; j < 50; j++)
            cr[j] = fmaxf(sO[t*SM_LDO + j] + bias[j], 0.0f);
        float l[5];
        #pragma unroll
        for (int k = 0; k < 5; k++) {
            float a = w2s[250 + k];
            #pragma unroll
            for (int j = 0; j < 50; j++) a += cr[j]*w2s[j*5 + k];
            l[k] = a;
        }
        float m = l[0];
        #pragma unroll
        for (int k = 1; k < 5; k++) m = fmaxf(m, l[k]);
        float e[5], s = 0.0f;
        #pragma unroll
        for (int k = 0; k < 5; k++) { e[k] = expf(l[k] - m); s += e[k]; }
        float inv = 1.0f/s;
        #pragma unroll
        for (int k = 0; k < 5; k++) g_S[(size_t)(m0 + t)*5 + k] = e[k]*inv;
    }
}

// ---------------- soft-cluster pooling ----------------
__global__ void cf_kernel() {
    int g = blockIdx.x, t = threadIdx.x;     // 640 threads
    __shared__ float sh[64*128];
    __shared__ float sS[64*5];
    int k = t >> 7, c = t & 127;
    float acc = 0.0f, ss = 0.0f;
    for (int ch = 0; ch < 8; ch++) {
        int nb = ch*64;
        const float* hb = g_h + ((size_t)g*NPGC + nb)*DD;
        for (int i = t; i < 64*128; i += 640) sh[i] = hb[i];
        const float* sb = g_S + ((size_t)g*NPGC + nb)*5;
        for (int i = t; i < 320; i += 640) sS[i] = sb[i];
        __syncthreads();
        for (int n2 = 0; n2 < 64; n2++) {
            float s = sS[n2*5 + k];
            acc += s*sh[n2*128 + c];
            ss  += s;
        }
        __syncthreads();
    }
    g_cf[((size_t)g*5 + k)*128 + c] = acc/(ss + 1e-6f);
}

// ---------------- VQ nearest codebook ----------------
__global__ void vq_kernel(const float* __restrict__ codebook) {
    int row = blockIdx.x;
    int t = threadIdx.x, w = t >> 5, lane = t & 31;
    __shared__ __align__(16) float f[128];
    __shared__ float wbest[4];
    __shared__ int   widx[4];
    __shared__ int   bestidx;
    f[t] = g_cf[(size_t)row*128 + t];
    __syncthreads();
    float4 fv = ((const float4*)f)[lane];
    float best = 3.4e38f;
    int bi = 0;
    for (int rr = w; rr < CBN; rr += 4) {
        const float4* cb4 = (const float4*)(codebook + (size_t)rr*128);
        float4 cv = cb4[lane];
        float dx = cv.x - fv.x, dy = cv.y - fv.y, dz = cv.z - fv.z, dw = cv.w - fv.w;
        float d = dx*dx + dy*dy + dz*dz + dw*dw;
        #pragma unroll
        for (int o = 16; o; o >>= 1) d += __shfl_xor_sync(0xffffffff, d, o);
        if (d < best) { best = d; bi = rr; }
    }
    if (lane == 0) { wbest[w] = best; widx[w] = bi; }
    __syncthreads();
    if (t == 0) {
        float bb = wbest[0]; int ii = widx[0];
        for (int j = 1; j < 4; j++)
            if (wbest[j] < bb || (wbest[j] == bb && widx[j] < ii)) { bb = wbest[j]; ii = widx[j]; }
        bestidx = ii;
    }
    __syncthreads();
    g_zq[(size_t)row*128 + t] = codebook[(size_t)bestidx*128 + t];
}

// ---------------- fused attention + gate + classifier (per-graph) ----------------
__global__ void tail_kernel(const float* __restrict__ Wq, const float* __restrict__ Wk,
                            const float* __restrict__ Wv, const float* __restrict__ Wo,
                            const float* __restrict__ gW1, const float* __restrict__ gb1,
                            const float* __restrict__ gW2, const float* __restrict__ gb2,
                            const float* __restrict__ cW1, const float* __restrict__ cb1,
                            const float* __restrict__ cW2, const float* __restrict__ cb2,
                            const float* __restrict__ cW3, const float* __restrict__ cb3,
                            float* __restrict__ out)
{
    int g = blockIdx.x, t = threadIdx.x;     // 128 threads
    __shared__ float r[128], zq5[5*128], qv[128], kk[5*128], vv[5*128];
    __shared__ float sc[20], aw[20], attv[128], attn[128], g1[64], fused[128];
    __shared__ float z1[512], z2[256];

    r[t] = g_res[g*128 + t]*(1.0f/NPGC);
    #pragma unroll
    for (int j = 0; j < 5; j++) zq5[j*128 + t] = g_zq[((size_t)g*5 + j)*128 + t];
    __syncthreads();

    {
        float a = 0.0f;
        for (int k2 = 0; k2 < 128; k2++) a += r[k2]*Wq[k2*128 + t];
        qv[t] = a;
    }
    {
        float a5[5] = {0,0,0,0,0};
        for (int k2 = 0; k2 < 128; k2++) {
            float wv2 = Wk[k2*128 + t];
            #pragma unroll
            for (int j = 0; j < 5; j++) a5[j] += zq5[j*128 + k2]*wv2;
        }
        #pragma unroll
        for (int j = 0; j < 5; j++) kk[j*128 + t] = a5[j];
    }
    {
        float a5[5] = {0,0,0,0,0};
        for (int k2 = 0; k2 < 128; k2++) {
            float wv2 = Wv[k2*128 + t];
            #pragma unroll
            for (int j = 0; j < 5; j++) a5[j] += zq5[j*128 + k2]*wv2;
        }
        #pragma unroll
        for (int j = 0; j < 5; j++) vv[j*128 + t] = a5[j];
    }
    __syncthreads();

    if (t < 20) {
        int hh = t/5, j = t%5;
        float s = 0.0f;
        for (int d2 = 0; d2 < 32; d2++) s += qv[hh*32 + d2]*kk[j*128 + hh*32 + d2];
        sc[t] = s*0.17677669529663687f;
    }
    __syncthreads();
    if (t < 4) {
        float m = -1e30f;
        #pragma unroll
        for (int j = 0; j < 5; j++) m = fmaxf(m, sc[t*5 + j]);
        float e[5], s = 0.0f;
        #pragma unroll
        for (int j = 0; j < 5; j++) { e[j] = expf(sc[t*5 + j] - m); s += e[j]; }
        float inv = 1.0f/s;
        #pragma unroll
        for (int j = 0; j < 5; j++) aw[t*5 + j] = e[j]*inv;
    }
    __syncthreads();
    {
        int hh = t >> 5;
        float a = 0.0f;
        #pragma unroll
        for (int j = 0; j < 5; j++) a += aw[hh*5 + j]*vv[j*128 + t];
        attv[t] = a;
    }
    __syncthreads();
    {
        float a = 0.0f;
        for (int k2 = 0; k2 < 128; k2++) a += attv[k2]*Wo[k2*128 + t];
        attn[t] = a;
    }
    __syncthreads();
    if (t < 64) {
        float a = gb1[t];
        for (int k2 = 0; k2 < 128; k2++) a += r[k2]*gW1[k2*64 + t];
        for (int k2 = 0; k2 < 128; k2++) a += attn[k2]*gW1[(128 + k2)*64 + t];
        g1[t] = fmaxf(a, 0.0f);
    }
    __syncthreads();
    {
        float a = gb2[t];
        for (int k2 = 0; k2 < 64; k2++) a += g1[k2]*gW2[k2*128 + t];
        float gg = 1.0f/(1.0f + expf(-a));
        fused[t] = gg*r[t] + (1.0f - gg)*attn[t];
    }
    __syncthreads();
    for (int o = t; o < 512; o += 128) {
        float a = cb1[o];
        for (int k2 = 0; k2 < 128; k2++) a += fused[k2]*cW1[k2*512 + o];
        z1[o] = fmaxf(a, 0.0f);
    }
    __syncthreads();
    for (int o = t; o < 256; o += 128) {
        float a = cb2[o];
        for (int k2 = 0; k2 < 512; k2++) a += z1[k2]*cW2[k2*256 + o];
        z2[o] = fmaxf(a, 0.0f);
    }
    __syncthreads();
    if (t < 2) {
        float a = cb3[t];
        for (int k2 = 0; k2 < 256; k2++) a += z2[k2]*cW3[k2*2 + t];
        out[g*2 + t] = a;
    }
}

// ---------------- host launch ----------------
extern "C" void kernel_launch(void* const* d_in, const int* in_sizes, int n_in,
                              void* d_out, int out_size) {
    (void)in_sizes; (void)n_in; (void)out_size;
    const int*   x     = (const int*)d_in[0];
    const int*   ei    = (const int*)d_in[1];
    const float* emb   = (const float*)d_in[3];
    const float* gW1   = (const float*)d_in[4];
    const float* gb1v  = (const float*)d_in[5];
    const float* gW2   = (const float*)d_in[6];
    const float* gb2v  = (const float*)d_in[7];
    const float* bng   = (const float*)d_in[8];
    const float* bnb   = (const float*)d_in[9];
    const float* pW1   = (const float*)d_in[10];
    const float* pb1   = (const float*)d_in[11];
    const float* pW2   = (const float*)d_in[12];
    const float* pb2   = (const float*)d_in[13];
    const float* Wq    = (const float*)d_in[14];
    const float* Wk    = (const float*)d_in[15];
    const float* Wv    = (const float*)d_in[16];
    const float* Wo    = (const float*)d_in[17];
    const float* gateW1= (const float*)d_in[18];
    const float* gateb1= (const float*)d_in[19];
    const float* gateW2= (const float*)d_in[20];
    const float* gateb2= (const float*)d_in[21];
    const float* cbk   = (const float*)d_in[22];
    const float* cW1   = (const float*)d_in[23];
    const float* cb1   = (const float*)d_in[24];
    const float* cW2   = (const float*)d_in[25];
    const float* cb2   = (const float*)d_in[26];
    const float* cW3   = (const float*)d_in[27];
    const float* cb3   = (const float*)d_in[28];
    float* out = (float*)d_out;

    bf16 *ahi, *alo, *w1hi, *w1lo, *w2hi, *w2lo, *pwhi, *pwlo;
    float *ppb1;
    cudaGetSymbolAddress((void**)&ahi,  g_ahi);
    cudaGetSymbolAddress((void**)&alo,  g_alo);
    cudaGetSymbolAddress((void**)&w1hi, g_w1hi);
    cudaGetSymbolAddress((void**)&w1lo, g_w1lo);
    cudaGetSymbolAddress((void**)&w2hi, g_w2hi);
    cudaGetSymbolAddress((void**)&w2lo, g_w2lo);
    cudaGetSymbolAddress((void**)&pwhi, g_pwhi);
    cudaGetSymbolAddress((void**)&pwlo, g_pwlo);
    cudaGetSymbolAddress((void**)&ppb1, g_pb1);

    cudaFuncSetAttribute(ginlayer,  cudaFuncAttributeMaxDynamicSharedMemorySize, GIN_SMEM);
    cudaFuncSetAttribute(part_gemm, cudaFuncAttributeMaxDynamicSharedMemorySize, SMEM_BYTES);

    csr_kernel<<<BB, 512>>>(ei);
    {
        int tot = NN*DD + 3*DD*H2D + 3*H2D*DD + DD*128 + 128;
        prep_embed<<<(tot + 255)/256, 256>>>(x, emb, gW1, gW2, pW1, pb1);
    }

    for (int l = 0; l < 3; l++) {
        ginlayer<<<NN/128, 512, GIN_SMEM>>>(
            w1hi + (size_t)l*DD*H2D, w1lo + (size_t)l*DD*H2D,
            w2hi + (size_t)l*H2D*DD, w2lo + (size_t)l*H2D*DD,
            gb1v + l*H2D, gb2v + l*DD, bng + l*DD, bnb + l*DD,
            (l == 2) ? 1 : 0);
    }

    part_gemm<<<NN/128, 256, SMEM_BYTES>>>(ahi, alo, pwhi, pwlo, ppb1, pW2, pb2);

    cf_kernel  <<<BB, 640>>>();
    vq_kernel  <<<BB*KCL, 128>>>(cbk);
    tail_kernel<<<BB, 128>>>(Wq, Wk, Wv, Wo, gateW1, gateb1, gateW2, gateb2,
                             cW1, cb1, cW2, cb2, cW3, cb3, out);
}

// round 6
// speedup vs baseline: 1.4949x; 1.4914x over previous
#include <cuda_runtime.h>
#include <cuda_bf16.h>
#include <mma.h>

using namespace nvcuda;

#define NN   32768
#define DD   128
#define BB   64
#define NPGC 512
#define EE   524288
#define KCL  5
#define H2D  256
#define CBN  512

typedef __nv_bfloat16 bf16;

// ---------------- scratch (device globals; no runtime allocation) ----------------
__device__ float g_h[NN*DD];
__device__ bf16  g_ahi[NN*DD],  g_alo[NN*DD];     // final-layer activation split (partitioner A)
__device__ float g_S[NN*KCL];
__device__ float g_cf[BB*KCL*DD];
__device__ float g_zq[BB*KCL*DD];
__device__ float g_res[BB*DD];
__device__ int   g_off[NN+1], g_srcl[EE];
__device__ bf16  g_w1hi[3*DD*H2D], g_w1lo[3*DD*H2D];
__device__ bf16  g_w2hi[3*H2D*DD], g_w2lo[3*H2D*DD];
__device__ bf16  g_pwhi[DD*128],   g_pwlo[DD*128];   // partitioner W1 padded 50->128
__device__ float g_pb1[128];

__device__ __forceinline__ void bsplit(float v, bf16& hi, bf16& lo) {
    hi = __float2bfloat16(v);
    lo = __float2bfloat16(v - __bfloat162float(hi));
}

// ---------------- per-graph CSR build (counting sort in smem) + zero g_res ----------------
__global__ void csr_kernel(const int* __restrict__ ei) {
    __shared__ int cnt[512];
    __shared__ int offs[512];
    int g = blockIdx.x, t = threadIdx.x;       // 64 blocks x 512 threads
    cnt[t] = 0;
    if (t < 128) g_res[g*128 + t] = 0.0f;
    __syncthreads();
    int ebase = g*8192;
    int nbase = g*512;
    #pragma unroll
    for (int i = 0; i < 16; i++) {
        int e = ebase + t + i*512;
        int d = ei[EE + e] - nbase;            // local dst (edges stay in-graph)
        atomicAdd(&cnt[d], 1);
    }
    __syncthreads();
    offs[t] = cnt[t];
    __syncthreads();
    for (int off = 1; off < 512; off <<= 1) {
        int v = (t >= off) ? offs[t-off] : 0;
        __syncthreads();
        offs[t] += v;
        __syncthreads();
    }
    int excl = offs[t] - cnt[t];
    g_off[nbase + t] = ebase + excl;
    if (g == BB-1 && t == 511) g_off[NN] = EE;
    cnt[t] = excl;                              // reuse as scatter cursor
    __syncthreads();
    #pragma unroll
    for (int i = 0; i < 16; i++) {
        int e = ebase + t + i*512;
        int d = ei[EE + e] - nbase;
        int p = atomicAdd(&cnt[d], 1);
        g_srcl[ebase + p] = ei[e];
    }
}

// ---------------- prep (weight splits) + embedding, merged ----------------
__global__ void prep_embed(const int* __restrict__ x, const float* __restrict__ emb,
                           const float* __restrict__ gW1, const float* __restrict__ gW2,
                           const float* __restrict__ pW1, const float* __restrict__ pb1) {
    int i = blockIdx.x*256 + threadIdx.x;
    if (i < NN*DD) { g_h[i] = emb[x[i >> 7]*DD + (i & 127)]; return; }
    i -= NN*DD;
    if (i < 3*DD*H2D) { bsplit(gW1[i], g_w1hi[i], g_w1lo[i]); return; }
    i -= 3*DD*H2D;
    if (i < 3*H2D*DD) { bsplit(gW2[i], g_w2hi[i], g_w2lo[i]); return; }
    i -= 3*H2D*DD;
    if (i < DD*128) {
        int rw = i >> 7, cl = i & 127;
        float v = (cl < 50) ? pW1[rw*50 + cl] : 0.0f;
        bsplit(v, g_pwhi[i], g_pwlo[i]);
        return;
    }
    i -= DD*128;
    if (i < 128) g_pb1[i] = (i < 50) ? pb1[i] : 0.0f;
}

// ---------------- fused GIN layer, M=64 tile, occ-2 ----------------
// 512 threads, 64 nodes/CTA, smem 102400 B -> 2 CTAs/SM.
// layout (bytes):
//   [0,17408)        sZh 64x136 bf16          (dies after gemm1)
//   [17408,34816)    sZl
//   [34816,68608)    sW1h chunk 64x264 bf16   (dies after gemm1)
//   [68608,102400)   sW1l chunk
//   after gemm1:
//   [0,33792)        sHh hidden 64x264 bf16
//   [33792,67584)    sHl
//   [67584,101376)   scrF 64x132 f32  /  sW2h+sW2l chunks 64x136 bf16 each
#define ZLD  136
#define WLD  264
#define W2LD 136
#define GIN2_SMEM 102400

__global__ __launch_bounds__(512, 2)
void ginlayer(const bf16* __restrict__ W1h, const bf16* __restrict__ W1l,
              const bf16* __restrict__ W2h, const bf16* __restrict__ W2l,
              const float* __restrict__ b1, const float* __restrict__ b2,
              const float* __restrict__ gamma, const float* __restrict__ beta,
              int last)
{
    extern __shared__ __align__(16) char smem[];
    bf16*  sZh  = (bf16*)smem;
    bf16*  sZl  = sZh + 64*ZLD;
    bf16*  sW1h = sZl + 64*ZLD;
    bf16*  sW1l = sW1h + 64*WLD;
    bf16*  sHh  = (bf16*)smem;
    bf16*  sHl  = sHh + 64*WLD;
    float* scrF = (float*)(smem + 4*64*WLD);     // byte 67584
    bf16*  sW2h = (bf16*)(smem + 4*64*WLD);
    bf16*  sW2l = sW2h + 64*W2LD;

    int t = threadIdx.x, w = t >> 5, lane = t & 31;
    int wm = w & 3, wn = w >> 2;                 // 4m x 4n warps
    int m0 = blockIdx.x*64;

    // ---- Phase A: gather z (4 nodes per warp) ----
    {
        const float4* __restrict__ h4 = (const float4*)g_h;
        #pragma unroll
        for (int i = 0; i < 4; i++) {
            int r = w*4 + i;
            int node = m0 + r;
            float4 a = h4[(size_t)node*32 + lane];
            int e0 = g_off[node], e1 = g_off[node+1];
            int j = e0;
            for (; j + 4 <= e1; j += 4) {
                int s0 = g_srcl[j+0], s1 = g_srcl[j+1], s2 = g_srcl[j+2], s3 = g_srcl[j+3];
                float4 v0 = h4[(size_t)s0*32 + lane];
                float4 v1 = h4[(size_t)s1*32 + lane];
                float4 v2 = h4[(size_t)s2*32 + lane];
                float4 v3 = h4[(size_t)s3*32 + lane];
                a.x += (v0.x + v1.x) + (v2.x + v3.x);
                a.y += (v0.y + v1.y) + (v2.y + v3.y);
                a.z += (v0.z + v1.z) + (v2.z + v3.z);
                a.w += (v0.w + v1.w) + (v2.w + v3.w);
            }
            for (; j < e1; j++) {
                int s = g_srcl[j];
                float4 v = h4[(size_t)s*32 + lane];
                a.x += v.x; a.y += v.y; a.z += v.z; a.w += v.w;
            }
            __nv_bfloat162* ph = (__nv_bfloat162*)(sZh + r*ZLD);
            __nv_bfloat162* pl = (__nv_bfloat162*)(sZl + r*ZLD);
            bf16 h0,l0,h1,l1;
            bsplit(a.x, h0, l0); bsplit(a.y, h1, l1);
            ph[lane*2]   = __halves2bfloat162(h0, h1);
            pl[lane*2]   = __halves2bfloat162(l0, l1);
            bsplit(a.z, h0, l0); bsplit(a.w, h1, l1);
            ph[lane*2+1] = __halves2bfloat162(h0, h1);
            pl[lane*2+1] = __halves2bfloat162(l0, l1);
        }
    }

    // ---- Phase B: gemm1  hidden[64x256] = z[64x128] @ W1[128x256], K in 2 chunks ----
    wmma::fragment<wmma::accumulator,16,16,16,float> acc1[4];
    #pragma unroll
    for (int j = 0; j < 4; j++) wmma::fill_fragment(acc1[j], 0.0f);

    #pragma unroll
    for (int c = 0; c < 2; c++) {
        __syncthreads();
        // stage W1 chunk rows [c*64, c*64+64): 64 x 32 uint4 per matrix
        #pragma unroll
        for (int i = 0; i < 4; i++) {
            int idx = t + i*512;               // 0..2047
            int r = idx >> 5, p = idx & 31;
            *(uint4*)(sW1h + r*WLD + p*8) = *(const uint4*)(W1h + (size_t)(c*64 + r)*256 + p*8);
            *(uint4*)(sW1l + r*WLD + p*8) = *(const uint4*)(W1l + (size_t)(c*64 + r)*256 + p*8);
        }
        __syncthreads();
        #pragma unroll
        for (int kb = 0; kb < 4; kb++) {
            wmma::fragment<wmma::matrix_a,16,16,16,bf16,wmma::row_major> ah, al;
            wmma::load_matrix_sync(ah, sZh + (wm*16)*ZLD + c*64 + kb*16, ZLD);
            wmma::load_matrix_sync(al, sZl + (wm*16)*ZLD + c*64 + kb*16, ZLD);
            #pragma unroll
            for (int jj = 0; jj < 2; jj++) {
                wmma::fragment<wmma::matrix_b,16,16,16,bf16,wmma::row_major> bh0, bh1, bl0, bl1;
                int nb = wn*64 + jj*32;
                wmma::load_matrix_sync(bh0, sW1h + (kb*16)*WLD + nb,      WLD);
                wmma::load_matrix_sync(bh1, sW1h + (kb*16)*WLD + nb + 16, WLD);
                wmma::load_matrix_sync(bl0, sW1l + (kb*16)*WLD + nb,      WLD);
                wmma::load_matrix_sync(bl1, sW1l + (kb*16)*WLD + nb + 16, WLD);
                wmma::mma_sync(acc1[jj*2+0], ah, bh0, acc1[jj*2+0]);
                wmma::mma_sync(acc1[jj*2+1], ah, bh1, acc1[jj*2+1]);
                wmma::mma_sync(acc1[jj*2+0], ah, bl0, acc1[jj*2+0]);
                wmma::mma_sync(acc1[jj*2+1], ah, bl1, acc1[jj*2+1]);
                wmma::mma_sync(acc1[jj*2+0], al, bh0, acc1[jj*2+0]);
                wmma::mma_sync(acc1[jj*2+1], al, bh1, acc1[jj*2+1]);
            }
        }
    }

    // ---- Phase C: hidden epilogue (bias+relu+split), 2 N-halves via scrF ----
    #pragma unroll
    for (int r = 0; r < 2; r++) {
        __syncthreads();
        if ((wn >> 1) == r) {
            #pragma unroll
            for (int j = 0; j < 4; j++)
                wmma::store_matrix_sync(scrF + (wm*16)*132 + (wn & 1)*64 + j*16,
                                        acc1[j], 132, wmma::mem_row_major);
        }
        __syncthreads();
        #pragma unroll 4
        for (int it = 0; it < 16; it++) {
            int idx = t + it*512;              // 0..8191
            int rr = idx >> 7, c = idx & 127;
            int C = r*128 + c;
            float v = fmaxf(scrF[rr*132 + c] + __ldg(b1 + C), 0.0f);
            bf16 hi, lo; bsplit(v, hi, lo);
            sHh[rr*WLD + C] = hi;
            sHl[rr*WLD + C] = lo;
        }
    }

    // ---- Phase D: gemm2  out[64x128] = hidden[64x256] @ W2[256x128], K in 4 chunks ----
    wmma::fragment<wmma::accumulator,16,16,16,float> acc2[2];
    #pragma unroll
    for (int j = 0; j < 2; j++) wmma::fill_fragment(acc2[j], 0.0f);

    #pragma unroll
    for (int c2 = 0; c2 < 4; c2++) {
        __syncthreads();
        // stage W2 chunk rows [c2*64, c2*64+64): 64 x 16 uint4 per matrix
        #pragma unroll
        for (int i = 0; i < 2; i++) {
            int idx = t + i*512;               // 0..1023
            int r = idx >> 4, p = idx & 15;
            *(uint4*)(sW2h + r*W2LD + p*8) = *(const uint4*)(W2h + (size_t)(c2*64 + r)*128 + p*8);
            *(uint4*)(sW2l + r*W2LD + p*8) = *(const uint4*)(W2l + (size_t)(c2*64 + r)*128 + p*8);
        }
        __syncthreads();
        #pragma unroll
        for (int kb = 0; kb < 4; kb++) {
            wmma::fragment<wmma::matrix_a,16,16,16,bf16,wmma::row_major> ah, al;
            wmma::load_matrix_sync(ah, sHh + (wm*16)*WLD + c2*64 + kb*16, WLD);
            wmma::load_matrix_sync(al, sHl + (wm*16)*WLD + c2*64 + kb*16, WLD);
            wmma::fragment<wmma::matrix_b,16,16,16,bf16,wmma::row_major> bh0, bh1, bl0, bl1;
            int nb = wn*32;
            wmma::load_matrix_sync(bh0, sW2h + (kb*16)*W2LD + nb,      W2LD);
            wmma::load_matrix_sync(bh1, sW2h + (kb*16)*W2LD + nb + 16, W2LD);
            wmma::load_matrix_sync(bl0, sW2l + (kb*16)*W2LD + nb,      W2LD);
            wmma::load_matrix_sync(bl1, sW2l + (kb*16)*W2LD + nb + 16, W2LD);
            wmma::mma_sync(acc2[0], ah, bh0, acc2[0]);
            wmma::mma_sync(acc2[1], ah, bh1, acc2[1]);
            wmma::mma_sync(acc2[0], ah, bl0, acc2[0]);
            wmma::mma_sync(acc2[1], ah, bl1, acc2[1]);
            wmma::mma_sync(acc2[0], al, bh0, acc2[0]);
            wmma::mma_sync(acc2[1], al, bh1, acc2[1]);
        }
    }
    __syncthreads();
    #pragma unroll
    for (int j = 0; j < 2; j++)
        wmma::store_matrix_sync(scrF + (wm*16)*132 + wn*32 + j*16, acc2[j],
                                132, wmma::mem_row_major);
    __syncthreads();

    // ---- Phase E: final epilogue (bias + BN [+relu]) -> g_h [+split, residue] ----
    const float BNS = 0.99999500003749971f;    // 1/sqrt(1+1e-5)
    int ccol = t & 127;
    float rsum = 0.0f;
    #pragma unroll 4
    for (int it = 0; it < 16; it++) {
        int idx = t + it*512;
        int r = idx >> 7;                      // 0..63
        float v = scrF[r*132 + ccol] + __ldg(b2 + ccol);
        v = v*(BNS*__ldg(gamma + ccol)) + __ldg(beta + ccol);
        if (!last) v = fmaxf(v, 0.0f);
        size_t gi = (size_t)(m0 + r)*128 + ccol;
        g_h[gi] = v;
        if (last) {
            bf16 hi, lo; bsplit(v, hi, lo);
            g_ahi[gi] = hi;
            g_alo[gi] = lo;
            rsum += v;
        }
    }
    if (last)
        atomicAdd(&g_res[(m0 >> 9)*128 + ccol], rsum);
}

// ---------------- partitioner GEMM (128x128, K=128, 3-split) + fused W2 GEMV + softmax ----------------
#define SM_LDA 136
#define SM_LDO 132
#define SMEM_BYTES (4*128*SM_LDA*2)

__global__ void part_gemm(const bf16* __restrict__ Ahi, const bf16* __restrict__ Alo,
                          const bf16* __restrict__ Bhi, const bf16* __restrict__ Blo,
                          const float* __restrict__ bias,
                          const float* __restrict__ pW2, const float* __restrict__ pb2)
{
    extern __shared__ __align__(16) char smem[];
    bf16* sAh = (bf16*)smem;
    bf16* sAl = sAh + 128*SM_LDA;
    bf16* sBh = sAl + 128*SM_LDA;
    bf16* sBl = sBh + 128*SM_LDA;
    float* sO  = (float*)smem;
    float* w2s = (float*)(smem + 128*SM_LDO*4);

    int t = threadIdx.x, w = t >> 5;
    int wm = w & 3, wn = w >> 2;
    int m0 = blockIdx.x*128;

    wmma::fragment<wmma::accumulator,16,16,16,float> acc[2][4];
    #pragma unroll
    for (int i = 0; i < 2; i++)
        #pragma unroll
        for (int j = 0; j < 4; j++)
            wmma::fill_fragment(acc[i][j], 0.0f);

    #pragma unroll
    for (int i = 0; i < 8; i++) {
        int idx = t + i*256;
        int r = idx >> 4, p = idx & 15;
        *(uint4*)(sAh + r*SM_LDA + p*8) = *(const uint4*)(Ahi + (size_t)(m0 + r)*128 + p*8);
        *(uint4*)(sAl + r*SM_LDA + p*8) = *(const uint4*)(Alo + (size_t)(m0 + r)*128 + p*8);
        *(uint4*)(sBh + r*SM_LDA + p*8) = *(const uint4*)(Bhi + (size_t)r*128 + p*8);
        *(uint4*)(sBl + r*SM_LDA + p*8) = *(const uint4*)(Blo + (size_t)r*128 + p*8);
    }
    __syncthreads();

    #pragma unroll
    for (int s = 0; s < 3; s++) {
        const bf16* Ap = (s == 2) ? sAl : sAh;
        const bf16* Bp = (s == 1) ? sBl : sBh;
        #pragma unroll
        for (int kb = 0; kb < 8; kb++) {
            wmma::fragment<wmma::matrix_a,16,16,16,bf16,wmma::row_major> af[2];
            wmma::fragment<wmma::matrix_b,16,16,16,bf16,wmma::row_major> bfr[4];
            #pragma unroll
            for (int i = 0; i < 2; i++)
                wmma::load_matrix_sync(af[i], Ap + (wm*32 + i*16)*SM_LDA + kb*16, SM_LDA);
            #pragma unroll
            for (int j = 0; j < 4; j++)
                wmma::load_matrix_sync(bfr[j], Bp + (kb*16)*SM_LDA + wn*32 + j*16, SM_LDA);
            #pragma unroll
            for (int i = 0; i < 2; i++)
                #pragma unroll
                for (int j = 0; j < 4; j++)
                    wmma::mma_sync(acc[i][j], af[i], bfr[j], acc[i][j]);
        }
    }
    __syncthreads();
    #pragma unroll
    for (int i = 0; i < 2; i++)
        #pragma unroll
        for (int j = 0; j < 4; j++)
            wmma::store_matrix_sync(sO + (wm*32 + i*16)*SM_LDO + wn*32 + j*16, acc[i][j],
                                    SM_LDO, wmma::mem_row_major);
    if (t < 255) w2s[t] = (t < 250) ? pW2[t] : pb2[t - 250];
    __syncthreads();

    if (t < 128) {
        float cr[50];
        #pragma unroll
        for (int j = 0; j < 50; j++)
            cr[j] = fmaxf(sO[t*SM_LDO + j] + bias[j], 0.0f);
        float l[5];
        #pragma unroll
        for (int k = 0; k < 5; k++) {
            float a = w2s[250 + k];
            #pragma unroll
            for (int j = 0; j < 50; j++) a += cr[j]*w2s[j*5 + k];
            l[k] = a;
        }
        float m = l[0];
        #pragma unroll
        for (int k = 1; k < 5; k++) m = fmaxf(m, l[k]);
        float e[5], s = 0.0f;
        #pragma unroll
        for (int k = 0; k < 5; k++) { e[k] = expf(l[k] - m); s += e[k]; }
        float inv = 1.0f/s;
        #pragma unroll
        for (int k = 0; k < 5; k++) g_S[(size_t)(m0 + t)*5 + k] = e[k]*inv;
    }
}

// ---------------- soft-cluster pooling ----------------
__global__ void cf_kernel() {
    int g = blockIdx.x, t = threadIdx.x;     // 640 threads
    __shared__ float sh[64*128];
    __shared__ float sS[64*5];
    int k = t >> 7, c = t & 127;
    float acc = 0.0f, ss = 0.0f;
    for (int ch = 0; ch < 8; ch++) {
        int nb = ch*64;
        const float* hb = g_h + ((size_t)g*NPGC + nb)*DD;
        for (int i = t; i < 64*128; i += 640) sh[i] = hb[i];
        const float* sb = g_S + ((size_t)g*NPGC + nb)*5;
        for (int i = t; i < 320; i += 640) sS[i] = sb[i];
        __syncthreads();
        for (int n2 = 0; n2 < 64; n2++) {
            float s = sS[n2*5 + k];
            acc += s*sh[n2*128 + c];
            ss  += s;
        }
        __syncthreads();
    }
    g_cf[((size_t)g*5 + k)*128 + c] = acc/(ss + 1e-6f);
}

// ---------------- VQ nearest codebook ----------------
__global__ void vq_kernel(const float* __restrict__ codebook) {
    int row = blockIdx.x;
    int t = threadIdx.x, w = t >> 5, lane = t & 31;
    __shared__ __align__(16) float f[128];
    __shared__ float wbest[4];
    __shared__ int   widx[4];
    __shared__ int   bestidx;
    f[t] = g_cf[(size_t)row*128 + t];
    __syncthreads();
    float4 fv = ((const float4*)f)[lane];
    float best = 3.4e38f;
    int bi = 0;
    for (int rr = w; rr < CBN; rr += 4) {
        const float4* cb4 = (const float4*)(codebook + (size_t)rr*128);
        float4 cv = cb4[lane];
        float dx = cv.x - fv.x, dy = cv.y - fv.y, dz = cv.z - fv.z, dw = cv.w - fv.w;
        float d = dx*dx + dy*dy + dz*dz + dw*dw;
        #pragma unroll
        for (int o = 16; o; o >>= 1) d += __shfl_xor_sync(0xffffffff, d, o);
        if (d < best) { best = d; bi = rr; }
    }
    if (lane == 0) { wbest[w] = best; widx[w] = bi; }
    __syncthreads();
    if (t == 0) {
        float bb = wbest[0]; int ii = widx[0];
        for (int j = 1; j < 4; j++)
            if (wbest[j] < bb || (wbest[j] == bb && widx[j] < ii)) { bb = wbest[j]; ii = widx[j]; }
        bestidx = ii;
    }
    __syncthreads();
    g_zq[(size_t)row*128 + t] = codebook[(size_t)bestidx*128 + t];
}

// ---------------- fused attention + gate + classifier (per-graph) ----------------
__global__ void tail_kernel(const float* __restrict__ Wq, const float* __restrict__ Wk,
                            const float* __restrict__ Wv, const float* __restrict__ Wo,
                            const float* __restrict__ gW1, const float* __restrict__ gb1,
                            const float* __restrict__ gW2, const float* __restrict__ gb2,
                            const float* __restrict__ cW1, const float* __restrict__ cb1,
                            const float* __restrict__ cW2, const float* __restrict__ cb2,
                            const float* __restrict__ cW3, const float* __restrict__ cb3,
                            float* __restrict__ out)
{
    int g = blockIdx.x, t = threadIdx.x;     // 128 threads
    __shared__ float r[128], zq5[5*128], qv[128], kk[5*128], vv[5*128];
    __shared__ float sc[20], aw[20], attv[128], attn[128], g1[64], fused[128];
    __shared__ float z1[512], z2[256];

    r[t] = g_res[g*128 + t]*(1.0f/NPGC);
    #pragma unroll
    for (int j = 0; j < 5; j++) zq5[j*128 + t] = g_zq[((size_t)g*5 + j)*128 + t];
    __syncthreads();

    {
        float a = 0.0f;
        for (int k2 = 0; k2 < 128; k2++) a += r[k2]*Wq[k2*128 + t];
        qv[t] = a;
    }
    {
        float a5[5] = {0,0,0,0,0};
        for (int k2 = 0; k2 < 128; k2++) {
            float wv2 = Wk[k2*128 + t];
            #pragma unroll
            for (int j = 0; j < 5; j++) a5[j] += zq5[j*128 + k2]*wv2;
        }
        #pragma unroll
        for (int j = 0; j < 5; j++) kk[j*128 + t] = a5[j];
    }
    {
        float a5[5] = {0,0,0,0,0};
        for (int k2 = 0; k2 < 128; k2++) {
            float wv2 = Wv[k2*128 + t];
            #pragma unroll
            for (int j = 0; j < 5; j++) a5[j] += zq5[j*128 + k2]*wv2;
        }
        #pragma unroll
        for (int j = 0; j < 5; j++) vv[j*128 + t] = a5[j];
    }
    __syncthreads();

    if (t < 20) {
        int hh = t/5, j = t%5;
        float s = 0.0f;
        for (int d2 = 0; d2 < 32; d2++) s += qv[hh*32 + d2]*kk[j*128 + hh*32 + d2];
        sc[t] = s*0.17677669529663687f;
    }
    __syncthreads();
    if (t < 4) {
        float m = -1e30f;
        #pragma unroll
        for (int j = 0; j < 5; j++) m = fmaxf(m, sc[t*5 + j]);
        float e[5], s = 0.0f;
        #pragma unroll
        for (int j = 0; j < 5; j++) { e[j] = expf(sc[t*5 + j] - m); s += e[j]; }
        float inv = 1.0f/s;
        #pragma unroll
        for (int j = 0; j < 5; j++) aw[t*5 + j] = e[j]*inv;
    }
    __syncthreads();
    {
        int hh = t >> 5;
        float a = 0.0f;
        #pragma unroll
        for (int j = 0; j < 5; j++) a += aw[hh*5 + j]*vv[j*128 + t];
        attv[t] = a;
    }
    __syncthreads();
    {
        float a = 0.0f;
        for (int k2 = 0; k2 < 128; k2++) a += attv[k2]*Wo[k2*128 + t];
        attn[t] = a;
    }
    __syncthreads();
    if (t < 64) {
        float a = gb1[t];
        for (int k2 = 0; k2 < 128; k2++) a += r[k2]*gW1[k2*64 + t];
        for (int k2 = 0; k2 < 128; k2++) a += attn[k2]*gW1[(128 + k2)*64 + t];
        g1[t] = fmaxf(a, 0.0f);
    }
    __syncthreads();
    {
        float a = gb2[t];
        for (int k2 = 0; k2 < 64; k2++) a += g1[k2]*gW2[k2*128 + t];
        float gg = 1.0f/(1.0f + expf(-a));
        fused[t] = gg*r[t] + (1.0f - gg)*attn[t];
    }
    __syncthreads();
    for (int o = t; o < 512; o += 128) {
        float a = cb1[o];
        for (int k2 = 0; k2 < 128; k2++) a += fused[k2]*cW1[k2*512 + o];
        z1[o] = fmaxf(a, 0.0f);
    }
    __syncthreads();
    for (int o = t; o < 256; o += 128) {
        float a = cb2[o];
        for (int k2 = 0; k2 < 512; k2++) a += z1[k2]*cW2[k2*256 + o];
        z2[o] = fmaxf(a, 0.0f);
    }
    __syncthreads();
    if (t < 2) {
        float a = cb3[t];
        for (int k2 = 0; k2 < 256; k2++) a += z2[k2]*cW3[k2*2 + t];
        out[g*2 + t] = a;
    }
}

// ---------------- host launch ----------------
extern "C" void kernel_launch(void* const* d_in, const int* in_sizes, int n_in,
                              void* d_out, int out_size) {
    (void)in_sizes; (void)n_in; (void)out_size;
    const int*   x     = (const int*)d_in[0];
    const int*   ei    = (const int*)d_in[1];
    const float* emb   = (const float*)d_in[3];
    const float* gW1   = (const float*)d_in[4];
    const float* gb1v  = (const float*)d_in[5];
    const float* gW2   = (const float*)d_in[6];
    const float* gb2v  = (const float*)d_in[7];
    const float* bng   = (const float*)d_in[8];
    const float* bnb   = (const float*)d_in[9];
    const float* pW1   = (const float*)d_in[10];
    const float* pb1   = (const float*)d_in[11];
    const float* pW2   = (const float*)d_in[12];
    const float* pb2   = (const float*)d_in[13];
    const float* Wq    = (const float*)d_in[14];
    const float* Wk    = (const float*)d_in[15];
    const float* Wv    = (const float*)d_in[16];
    const float* Wo    = (const float*)d_in[17];
    const float* gateW1= (const float*)d_in[18];
    const float* gateb1= (const float*)d_in[19];
    const float* gateW2= (const float*)d_in[20];
    const float* gateb2= (const float*)d_in[21];
    const float* cbk   = (const float*)d_in[22];
    const float* cW1   = (const float*)d_in[23];
    const float* cb1   = (const float*)d_in[24];
    const float* cW2   = (const float*)d_in[25];
    const float* cb2   = (const float*)d_in[26];
    const float* cW3   = (const float*)d_in[27];
    const float* cb3   = (const float*)d_in[28];
    float* out = (float*)d_out;

    bf16 *ahi, *alo, *w1hi, *w1lo, *w2hi, *w2lo, *pwhi, *pwlo;
    float *ppb1;
    cudaGetSymbolAddress((void**)&ahi,  g_ahi);
    cudaGetSymbolAddress((void**)&alo,  g_alo);
    cudaGetSymbolAddress((void**)&w1hi, g_w1hi);
    cudaGetSymbolAddress((void**)&w1lo, g_w1lo);
    cudaGetSymbolAddress((void**)&w2hi, g_w2hi);
    cudaGetSymbolAddress((void**)&w2lo, g_w2lo);
    cudaGetSymbolAddress((void**)&pwhi, g_pwhi);
    cudaGetSymbolAddress((void**)&pwlo, g_pwlo);
    cudaGetSymbolAddress((void**)&ppb1, g_pb1);

    cudaFuncSetAttribute(ginlayer,  cudaFuncAttributeMaxDynamicSharedMemorySize, GIN2_SMEM);
    cudaFuncSetAttribute(part_gemm, cudaFuncAttributeMaxDynamicSharedMemorySize, SMEM_BYTES);

    csr_kernel<<<BB, 512>>>(ei);
    {
        int tot = NN*DD + 3*DD*H2D + 3*H2D*DD + DD*128 + 128;
        prep_embed<<<(tot + 255)/256, 256>>>(x, emb, gW1, gW2, pW1, pb1);
    }

    for (int l = 0; l < 3; l++) {
        ginlayer<<<NN/64, 512, GIN2_SMEM>>>(
            w1hi + (size_t)l*DD*H2D, w1lo + (size_t)l*DD*H2D,
            w2hi + (size_t)l*H2D*DD, w2lo + (size_t)l*H2D*DD,
            gb1v + l*H2D, gb2v + l*DD, bng + l*DD, bnb + l*DD,
            (l == 2) ? 1 : 0);
    }

    part_gemm<<<NN/128, 256, SMEM_BYTES>>>(ahi, alo, pwhi, pwlo, ppb1, pW2, pb2);

    cf_kernel  <<<BB, 640>>>();
    vq_kernel  <<<BB*KCL, 128>>>(cbk);
    tail_kernel<<<BB, 128>>>(Wq, Wk, Wv, Wo, gateW1, gateb1, gateW2, gateb2,
                             cW1, cb1, cW2, cb2, cW3, cb3, out);
}

// round 7
// speedup vs baseline: 1.5696x; 1.0500x over previous
#include <cuda_runtime.h>
#include <cuda_bf16.h>
#include <mma.h>

using namespace nvcuda;

#define NN   32768
#define DD   128
#define BB   64
#define NPGC 512
#define EE   524288
#define KCL  5
#define H2D  256
#define CBN  512

typedef __nv_bfloat16 bf16;

// ---------------- scratch (device globals; no runtime allocation) ----------------
__device__ float g_h[NN*DD];
__device__ float g_S[NN*KCL];
__device__ float g_res[BB*DD];
__device__ int   g_off[NN+1], g_srcl[EE];
__device__ bf16  g_w1hi[3*DD*H2D], g_w1lo[3*DD*H2D];
__device__ bf16  g_w2hi[3*H2D*DD], g_w2lo[3*H2D*DD];
__device__ bf16  g_pwhi[DD*128],   g_pwlo[DD*128];   // partitioner W1 padded 50->128
__device__ float g_pb1[128];

__device__ __forceinline__ void bsplit(float v, bf16& hi, bf16& lo) {
    hi = __float2bfloat16(v);
    lo = __float2bfloat16(v - __bfloat162float(hi));
}

// ---------------- per-graph CSR build (counting sort in smem) + zero g_res ----------------
__global__ void csr_kernel(const int* __restrict__ ei) {
    __shared__ int cnt[512];
    __shared__ int offs[512];
    int g = blockIdx.x, t = threadIdx.x;       // 64 blocks x 512 threads
    cnt[t] = 0;
    if (t < 128) g_res[g*128 + t] = 0.0f;
    __syncthreads();
    int ebase = g*8192;
    int nbase = g*512;
    #pragma unroll
    for (int i = 0; i < 16; i++) {
        int e = ebase + t + i*512;
        int d = ei[EE + e] - nbase;            // local dst (edges stay in-graph)
        atomicAdd(&cnt[d], 1);
    }
    __syncthreads();
    offs[t] = cnt[t];
    __syncthreads();
    for (int off = 1; off < 512; off <<= 1) {
        int v = (t >= off) ? offs[t-off] : 0;
        __syncthreads();
        offs[t] += v;
        __syncthreads();
    }
    int excl = offs[t] - cnt[t];
    g_off[nbase + t] = ebase + excl;
    if (g == BB-1 && t == 511) g_off[NN] = EE;
    cnt[t] = excl;                              // reuse as scatter cursor
    __syncthreads();
    #pragma unroll
    for (int i = 0; i < 16; i++) {
        int e = ebase + t + i*512;
        int d = ei[EE + e] - nbase;
        int p = atomicAdd(&cnt[d], 1);
        g_srcl[ebase + p] = ei[e];
    }
}

// ---------------- prep (weight splits) + embedding, merged ----------------
__global__ void prep_embed(const int* __restrict__ x, const float* __restrict__ emb,
                           const float* __restrict__ gW1, const float* __restrict__ gW2,
                           const float* __restrict__ pW1, const float* __restrict__ pb1) {
    int i = blockIdx.x*256 + threadIdx.x;
    if (i < NN*DD) { g_h[i] = emb[x[i >> 7]*DD + (i & 127)]; return; }
    i -= NN*DD;
    if (i < 3*DD*H2D) { bsplit(gW1[i], g_w1hi[i], g_w1lo[i]); return; }
    i -= 3*DD*H2D;
    if (i < 3*H2D*DD) { bsplit(gW2[i], g_w2hi[i], g_w2lo[i]); return; }
    i -= 3*H2D*DD;
    if (i < DD*128) {
        int rw = i >> 7, cl = i & 127;
        float v = (cl < 50) ? pW1[rw*50 + cl] : 0.0f;
        bsplit(v, g_pwhi[i], g_pwlo[i]);
        return;
    }
    i -= DD*128;
    if (i < 128) g_pb1[i] = (i < 50) ? pb1[i] : 0.0f;
}

// ---------------- fused GIN layer, M=64 tile, occ-2, fused partitioner on last ----------------
// 512 threads, 64 nodes/CTA, smem 102400 B -> 2 CTAs/SM.
//   [0,17408)        sZh 64x136 bf16          (z; later hidden-hi overlaps; later act-hi for partitioner)
//   [17408,34816)    sZl
//   [34816,68608)    sW1h chunk 64x264 bf16
//   [68608,102400)   sW1l chunk
//   hidden aliases [0,67584) at pitch 264; scrF f32 64x132 at [67584,101376)
//   partitioner: sPh [34816,52224), sPl [52224,69632); w2s [101376,102396)
#define ZLD  136
#define WLD  264
#define W2LD 136
#define GIN2_SMEM 102400

__global__ __launch_bounds__(512, 2)
void ginlayer(const bf16* __restrict__ W1h, const bf16* __restrict__ W1l,
              const bf16* __restrict__ W2h, const bf16* __restrict__ W2l,
              const float* __restrict__ b1, const float* __restrict__ b2,
              const float* __restrict__ gamma, const float* __restrict__ beta,
              const bf16* __restrict__ Ph, const bf16* __restrict__ Pl,
              const float* __restrict__ pbias, const float* __restrict__ pW2,
              const float* __restrict__ pb2, int last)
{
    extern __shared__ __align__(16) char smem[];
    bf16*  sZh  = (bf16*)smem;
    bf16*  sZl  = sZh + 64*ZLD;
    bf16*  sW1h = sZl + 64*ZLD;
    bf16*  sW1l = sW1h + 64*WLD;
    bf16*  sHh  = (bf16*)smem;
    bf16*  sHl  = sHh + 64*WLD;
    float* scrF = (float*)(smem + 4*64*WLD);     // byte 67584
    bf16*  sW2h = (bf16*)(smem + 4*64*WLD);
    bf16*  sW2l = sW2h + 64*W2LD;
    bf16*  sPh  = (bf16*)(smem + 34816);
    bf16*  sPl  = sPh + 64*W2LD;
    float* w2s  = (float*)(smem + 101376);

    int t = threadIdx.x, w = t >> 5, lane = t & 31;
    int m0 = blockIdx.x*64;

    // ---- Phase A: gather z (4 nodes per warp) ----
    {
        const float4* __restrict__ h4 = (const float4*)g_h;
        #pragma unroll
        for (int i = 0; i < 4; i++) {
            int r = w*4 + i;
            int node = m0 + r;
            float4 a = h4[(size_t)node*32 + lane];
            int e0 = g_off[node], e1 = g_off[node+1];
            int j = e0;
            for (; j + 4 <= e1; j += 4) {
                int s0 = g_srcl[j+0], s1 = g_srcl[j+1], s2 = g_srcl[j+2], s3 = g_srcl[j+3];
                float4 v0 = h4[(size_t)s0*32 + lane];
                float4 v1 = h4[(size_t)s1*32 + lane];
                float4 v2 = h4[(size_t)s2*32 + lane];
                float4 v3 = h4[(size_t)s3*32 + lane];
                a.x += (v0.x + v1.x) + (v2.x + v3.x);
                a.y += (v0.y + v1.y) + (v2.y + v3.y);
                a.z += (v0.z + v1.z) + (v2.z + v3.z);
                a.w += (v0.w + v1.w) + (v2.w + v3.w);
            }
            for (; j < e1; j++) {
                int s = g_srcl[j];
                float4 v = h4[(size_t)s*32 + lane];
                a.x += v.x; a.y += v.y; a.z += v.z; a.w += v.w;
            }
            __nv_bfloat162* ph = (__nv_bfloat162*)(sZh + r*ZLD);
            __nv_bfloat162* pl = (__nv_bfloat162*)(sZl + r*ZLD);
            bf16 h0,l0,h1,l1;
            bsplit(a.x, h0, l0); bsplit(a.y, h1, l1);
            ph[lane*2]   = __halves2bfloat162(h0, h1);
            pl[lane*2]   = __halves2bfloat162(l0, l1);
            bsplit(a.z, h0, l0); bsplit(a.w, h1, l1);
            ph[lane*2+1] = __halves2bfloat162(h0, h1);
            pl[lane*2+1] = __halves2bfloat162(l0, l1);
        }
    }

    // ---- Phase B: gemm1  hidden[64x256] = z[64x128] @ W1[128x256], warp tile 32x32 ----
    {
        int wm1 = w >> 3, wn1 = w & 7;               // 2 x 8 warps
        wmma::fragment<wmma::accumulator,16,16,16,float> acc1[2][2];
        #pragma unroll
        for (int i = 0; i < 2; i++)
            #pragma unroll
            for (int j = 0; j < 2; j++)
                wmma::fill_fragment(acc1[i][j], 0.0f);

        #pragma unroll
        for (int c = 0; c < 2; c++) {
            __syncthreads();
            #pragma unroll
            for (int i = 0; i < 4; i++) {
                int idx = t + i*512;                 // 2048 uint4 per matrix
                int r = idx >> 5, p = idx & 31;
                *(uint4*)(sW1h + r*WLD + p*8) = *(const uint4*)(W1h + (size_t)(c*64 + r)*256 + p*8);
                *(uint4*)(sW1l + r*WLD + p*8) = *(const uint4*)(W1l + (size_t)(c*64 + r)*256 + p*8);
            }
            __syncthreads();
            #pragma unroll
            for (int kb = 0; kb < 4; kb++) {
                wmma::fragment<wmma::matrix_a,16,16,16,bf16,wmma::row_major> ah[2], al[2];
                #pragma unroll
                for (int i = 0; i < 2; i++) {
                    wmma::load_matrix_sync(ah[i], sZh + (wm1*32 + i*16)*ZLD + c*64 + kb*16, ZLD);
                    wmma::load_matrix_sync(al[i], sZl + (wm1*32 + i*16)*ZLD + c*64 + kb*16, ZLD);
                }
                wmma::fragment<wmma::matrix_b,16,16,16,bf16,wmma::row_major> bh[2], bl[2];
                #pragma unroll
                for (int j = 0; j < 2; j++) {
                    wmma::load_matrix_sync(bh[j], sW1h + (kb*16)*WLD + wn1*32 + j*16, WLD);
                    wmma::load_matrix_sync(bl[j], sW1l + (kb*16)*WLD + wn1*32 + j*16, WLD);
                }
                #pragma unroll
                for (int i = 0; i < 2; i++)
                    #pragma unroll
                    for (int j = 0; j < 2; j++) {
                        wmma::mma_sync(acc1[i][j], ah[i], bh[j], acc1[i][j]);
                        wmma::mma_sync(acc1[i][j], ah[i], bl[j], acc1[i][j]);
                        wmma::mma_sync(acc1[i][j], al[i], bh[j], acc1[i][j]);
                    }
            }
        }

        // ---- Phase C: hidden epilogue (bias+relu+split), 2 N-halves via scrF ----
        #pragma unroll
        for (int r = 0; r < 2; r++) {
            __syncthreads();
            if ((wn1 >> 2) == r) {
                #pragma unroll
                for (int i = 0; i < 2; i++)
                    #pragma unroll
                    for (int j = 0; j < 2; j++)
                        wmma::store_matrix_sync(scrF + (wm1*32 + i*16)*132 + (wn1 & 3)*32 + j*16,
                                                acc1[i][j], 132, wmma::mem_row_major);
            }
            __syncthreads();
            #pragma unroll 4
            for (int it = 0; it < 16; it++) {
                int idx = t + it*512;
                int rr = idx >> 7, c = idx & 127;
                int C = r*128 + c;
                float v = fmaxf(scrF[rr*132 + c] + __ldg(b1 + C), 0.0f);
                bf16 hi, lo; bsplit(v, hi, lo);
                sHh[rr*WLD + C] = hi;
                sHl[rr*WLD + C] = lo;
            }
        }
    }

    // ---- Phase D: gemm2  out[64x128] = hidden[64x256] @ W2[256x128], warp tile 16x32 ----
    {
        int wm = w & 3, wn = w >> 2;                 // 4 x 4 warps
        wmma::fragment<wmma::accumulator,16,16,16,float> acc2[2];
        #pragma unroll
        for (int j = 0; j < 2; j++) wmma::fill_fragment(acc2[j], 0.0f);

        #pragma unroll
        for (int c2 = 0; c2 < 4; c2++) {
            __syncthreads();
            #pragma unroll
            for (int i = 0; i < 2; i++) {
                int idx = t + i*512;
                int r = idx >> 4, p = idx & 15;
                *(uint4*)(sW2h + r*W2LD + p*8) = *(const uint4*)(W2h + (size_t)(c2*64 + r)*128 + p*8);
                *(uint4*)(sW2l + r*W2LD + p*8) = *(const uint4*)(W2l + (size_t)(c2*64 + r)*128 + p*8);
            }
            __syncthreads();
            #pragma unroll
            for (int kb = 0; kb < 4; kb++) {
                wmma::fragment<wmma::matrix_a,16,16,16,bf16,wmma::row_major> ah, al;
                wmma::load_matrix_sync(ah, sHh + (wm*16)*WLD + c2*64 + kb*16, WLD);
                wmma::load_matrix_sync(al, sHl + (wm*16)*WLD + c2*64 + kb*16, WLD);
                wmma::fragment<wmma::matrix_b,16,16,16,bf16,wmma::row_major> bh0, bh1, bl0, bl1;
                int nb = wn*32;
                wmma::load_matrix_sync(bh0, sW2h + (kb*16)*W2LD + nb,      W2LD);
                wmma::load_matrix_sync(bh1, sW2h + (kb*16)*W2LD + nb + 16, W2LD);
                wmma::load_matrix_sync(bl0, sW2l + (kb*16)*W2LD + nb,      W2LD);
                wmma::load_matrix_sync(bl1, sW2l + (kb*16)*W2LD + nb + 16, W2LD);
                wmma::mma_sync(acc2[0], ah, bh0, acc2[0]);
                wmma::mma_sync(acc2[1], ah, bh1, acc2[1]);
                wmma::mma_sync(acc2[0], ah, bl0, acc2[0]);
                wmma::mma_sync(acc2[1], ah, bl1, acc2[1]);
                wmma::mma_sync(acc2[0], al, bh0, acc2[0]);
                wmma::mma_sync(acc2[1], al, bh1, acc2[1]);
            }
        }
        __syncthreads();
        #pragma unroll
        for (int j = 0; j < 2; j++)
            wmma::store_matrix_sync(scrF + (wm*16)*132 + wn*32 + j*16, acc2[j],
                                    132, wmma::mem_row_major);
        __syncthreads();
    }

    // ---- Phase E: final epilogue (bias + BN [+relu]) -> g_h [+ act-split to smem, residue] ----
    const float BNS = 0.99999500003749971f;    // 1/sqrt(1+1e-5)
    {
        int ccol = t & 127;
        float rsum = 0.0f;
        #pragma unroll 4
        for (int it = 0; it < 16; it++) {
            int idx = t + it*512;
            int r = idx >> 7;                      // 0..63
            float v = scrF[r*132 + ccol] + __ldg(b2 + ccol);
            v = v*(BNS*__ldg(gamma + ccol)) + __ldg(beta + ccol);
            if (!last) v = fmaxf(v, 0.0f);
            size_t gi = (size_t)(m0 + r)*128 + ccol;
            g_h[gi] = v;
            if (last) {
                bf16 hi, lo; bsplit(v, hi, lo);
                sZh[r*ZLD + ccol] = hi;            // act split -> z region (hidden dead)
                sZl[r*ZLD + ccol] = lo;
                rsum += v;
            }
        }
        if (last)
            atomicAdd(&g_res[(m0 >> 9)*128 + ccol], rsum);
    }

    if (!last) return;

    // ---- Phase F: fused partitioner  cl[64x128] = act[64x128] @ pW1[128x128] ----
    {
        int wm1 = w >> 3, wn1 = w & 7;               // 2 x 8 warps, warp tile 32x16
        wmma::fragment<wmma::accumulator,16,16,16,float> acc3[2];
        #pragma unroll
        for (int i = 0; i < 2; i++) wmma::fill_fragment(acc3[i], 0.0f);

        #pragma unroll
        for (int c = 0; c < 2; c++) {
            __syncthreads();
            #pragma unroll
            for (int i = 0; i < 2; i++) {            // 1024 uint4 per matrix
                int idx = t + i*512;
                int r = idx >> 4, p = idx & 15;
                *(uint4*)(sPh + r*W2LD + p*8) = *(const uint4*)(Ph + (size_t)(c*64 + r)*128 + p*8);
                *(uint4*)(sPl + r*W2LD + p*8) = *(const uint4*)(Pl + (size_t)(c*64 + r)*128 + p*8);
            }
            __syncthreads();
            #pragma unroll
            for (int kb = 0; kb < 4; kb++) {
                wmma::fragment<wmma::matrix_a,16,16,16,bf16,wmma::row_major> ah[2], al[2];
                #pragma unroll
                for (int i = 0; i < 2; i++) {
                    wmma::load_matrix_sync(ah[i], sZh + (wm1*32 + i*16)*ZLD + c*64 + kb*16, ZLD);
                    wmma::load_matrix_sync(al[i], sZl + (wm1*32 + i*16)*ZLD + c*64 + kb*16, ZLD);
                }
                wmma::fragment<wmma::matrix_b,16,16,16,bf16,wmma::row_major> bh, bl;
                wmma::load_matrix_sync(bh, sPh + (kb*16)*W2LD + wn1*16, W2LD);
                wmma::load_matrix_sync(bl, sPl + (kb*16)*W2LD + wn1*16, W2LD);
                #pragma unroll
                for (int i = 0; i < 2; i++) {
                    wmma::mma_sync(acc3[i], ah[i], bh, acc3[i]);
                    wmma::mma_sync(acc3[i], ah[i], bl, acc3[i]);
                    wmma::mma_sync(acc3[i], al[i], bh, acc3[i]);
                }
            }
        }
        __syncthreads();
        #pragma unroll
        for (int i = 0; i < 2; i++)
            wmma::store_matrix_sync(scrF + (wm1*32 + i*16)*132 + wn1*16, acc3[i],
                                    132, wmma::mem_row_major);
        if (t < 255) w2s[t] = (t < 250) ? pW2[t] : pb2[t - 250];
        __syncthreads();

        if (t < 64) {
            float cr[50];
            #pragma unroll
            for (int j = 0; j < 50; j++)
                cr[j] = fmaxf(scrF[t*132 + j] + pbias[j], 0.0f);
            float l[5];
            #pragma unroll
            for (int k = 0; k < 5; k++) {
                float a = w2s[250 + k];
                #pragma unroll
                for (int j = 0; j < 50; j++) a += cr[j]*w2s[j*5 + k];
                l[k] = a;
            }
            float m = l[0];
            #pragma unroll
            for (int k = 1; k < 5; k++) m = fmaxf(m, l[k]);
            float e[5], s = 0.0f;
            #pragma unroll
            for (int k = 0; k < 5; k++) { e[k] = expf(l[k] - m); s += e[k]; }
            float inv = 1.0f/s;
            #pragma unroll
            for (int k = 0; k < 5; k++) g_S[(size_t)(m0 + t)*5 + k] = e[k]*inv;
        }
    }
}

// ---------------- finale: cf pooling + VQ + attention/gate/classifier, one block per graph ----------------
__global__ void finale_kernel(const float* __restrict__ codebook,
                              const float* __restrict__ Wq, const float* __restrict__ Wk,
                              const float* __restrict__ Wv, const float* __restrict__ Wo,
                              const float* __restrict__ gW1, const float* __restrict__ gb1,
                              const float* __restrict__ gW2, const float* __restrict__ gb2,
                              const float* __restrict__ cW1, const float* __restrict__ cb1,
                              const float* __restrict__ cW2, const float* __restrict__ cb2,
                              const float* __restrict__ cW3, const float* __restrict__ cb3,
                              float* __restrict__ out)
{
    __shared__ __align__(16) float sh[64*128];       // cf staging, later tail scratch
    __shared__ float sS[64*5];
    __shared__ __align__(16) float cfv[5*128];
    __shared__ float zq5[5*128];
    __shared__ float wbest[5][4];
    __shared__ int   widx[5][4];
    __shared__ int   bidx[5];

    int g = blockIdx.x, t = threadIdx.x;             // 640 threads
    int k = t >> 7, c = t & 127;

    // ---- cf: soft-cluster pooling ----
    {
        float acc = 0.0f, ss = 0.0f;
        for (int ch = 0; ch < 8; ch++) {
            int nb = ch*64;
            const float* hb = g_h + ((size_t)g*NPGC + nb)*DD;
            for (int i = t; i < 64*128; i += 640) sh[i] = hb[i];
            const float* sb = g_S + ((size_t)g*NPGC + nb)*5;
            for (int i = t; i < 320; i += 640) sS[i] = sb[i];
            __syncthreads();
            for (int n2 = 0; n2 < 64; n2++) {
                float s = sS[n2*5 + k];
                acc += s*sh[n2*128 + c];
                ss  += s;
            }
            __syncthreads();
        }
        cfv[k*128 + c] = acc/(ss + 1e-6f);
    }
    __syncthreads();

    // ---- VQ: nearest codebook row per cluster (5 rows x 4 warps each) ----
    {
        int w4 = c >> 5, lane = c & 31;
        float4 fv = ((const float4*)(cfv + k*128))[lane];
        float best = 3.4e38f;
        int bi = 0;
        for (int rr = w4; rr < CBN; rr += 4) {
            const float4* cb4 = (const float4*)(codebook + (size_t)rr*128);
            float4 cv = cb4[lane];
            float dx = cv.x - fv.x, dy = cv.y - fv.y, dz = cv.z - fv.z, dw = cv.w - fv.w;
            float d = dx*dx + dy*dy + dz*dz + dw*dw;
            #pragma unroll
            for (int o = 16; o; o >>= 1) d += __shfl_xor_sync(0xffffffff, d, o);
            if (d < best) { best = d; bi = rr; }
        }
        if (lane == 0) { wbest[k][w4] = best; widx[k][w4] = bi; }
        __syncthreads();
        if (t < 5) {
            float bb = wbest[t][0]; int ii = widx[t][0];
            for (int j = 1; j < 4; j++)
                if (wbest[t][j] < bb || (wbest[t][j] == bb && widx[t][j] < ii)) { bb = wbest[t][j]; ii = widx[t][j]; }
            bidx[t] = ii;
        }
        __syncthreads();
        zq5[k*128 + c] = codebook[(size_t)bidx[k]*128 + c];
    }
    __syncthreads();

    // ---- tail: attention + gate + classifier (sh region reused as scratch) ----
    float* r    = sh;            // 128
    float* qv   = sh + 128;      // 128
    float* kk   = sh + 256;      // 640
    float* vv   = sh + 896;      // 640
    float* sc   = sh + 1536;     // 20
    float* aw   = sh + 1568;     // 20
    float* attv = sh + 1600;     // 128
    float* attn = sh + 1728;     // 128
    float* g1   = sh + 1856;     // 64
    float* fus  = sh + 1920;     // 128
    float* z1   = sh + 2048;     // 512
    float* z2   = sh + 2560;     // 256

    if (t < 128) r[t] = g_res[g*128 + t]*(1.0f/NPGC);
    __syncthreads();

    if (t < 128) {
        float a = 0.0f;
        for (int k2 = 0; k2 < 128; k2++) a += r[k2]*Wq[k2*128 + t];
        qv[t] = a;
        float a5[5] = {0,0,0,0,0};
        for (int k2 = 0; k2 < 128; k2++) {
            float wv2 = Wk[k2*128 + t];
            #pragma unroll
            for (int j = 0; j < 5; j++) a5[j] += zq5[j*128 + k2]*wv2;
        }
        #pragma unroll
        for (int j = 0; j < 5; j++) kk[j*128 + t] = a5[j];
        float b5[5] = {0,0,0,0,0};
        for (int k2 = 0; k2 < 128; k2++) {
            float wv2 = Wv[k2*128 + t];
            #pragma unroll
            for (int j = 0; j < 5; j++) b5[j] += zq5[j*128 + k2]*wv2;
        }
        #pragma unroll
        for (int j = 0; j < 5; j++) vv[j*128 + t] = b5[j];
    }
    __syncthreads();

    if (t < 20) {
        int hh = t/5, j = t%5;
        float s = 0.0f;
        for (int d2 = 0; d2 < 32; d2++) s += qv[hh*32 + d2]*kk[j*128 + hh*32 + d2];
        sc[t] = s*0.17677669529663687f;              // 1/sqrt(32)
    }
    __syncthreads();
    if (t < 4) {
        float m = -1e30f;
        #pragma unroll
        for (int j = 0; j < 5; j++) m = fmaxf(m, sc[t*5 + j]);
        float e[5], s = 0.0f;
        #pragma unroll
        for (int j = 0; j < 5; j++) { e[j] = expf(sc[t*5 + j] - m); s += e[j]; }
        float inv = 1.0f/s;
        #pragma unroll
        for (int j = 0; j < 5; j++) aw[t*5 + j] = e[j]*inv;
    }
    __syncthreads();
    if (t < 128) {
        int hh = t >> 5;
        float a = 0.0f;
        #pragma unroll
        for (int j = 0; j < 5; j++) a += aw[hh*5 + j]*vv[j*128 + t];
        attv[t] = a;
    }
    __syncthreads();
    if (t < 128) {
        float a = 0.0f;
        for (int k2 = 0; k2 < 128; k2++) a += attv[k2]*Wo[k2*128 + t];
        attn[t] = a;
    }
    __syncthreads();
    if (t < 64) {
        float a = gb1[t];
        for (int k2 = 0; k2 < 128; k2++) a += r[k2]*gW1[k2*64 + t];
        for (int k2 = 0; k2 < 128; k2++) a += attn[k2]*gW1[(128 + k2)*64 + t];
        g1[t] = fmaxf(a, 0.0f);
    }
    __syncthreads();
    if (t < 128) {
        float a = gb2[t];
        for (int k2 = 0; k2 < 64; k2++) a += g1[k2]*gW2[k2*128 + t];
        float gg = 1.0f/(1.0f + expf(-a));
        fus[t] = gg*r[t] + (1.0f - gg)*attn[t];
    }
    __syncthreads();
    if (t < 512) {
        float a = cb1[t];
        for (int k2 = 0; k2 < 128; k2++) a += fus[k2]*cW1[k2*512 + t];
        z1[t] = fmaxf(a, 0.0f);
    }
    __syncthreads();
    if (t < 256) {
        float a = cb2[t];
        for (int k2 = 0; k2 < 512; k2++) a += z1[k2]*cW2[k2*256 + t];
        z2[t] = fmaxf(a, 0.0f);
    }
    __syncthreads();
    if (t < 2) {
        float a = cb3[t];
        for (int k2 = 0; k2 < 256; k2++) a += z2[k2]*cW3[k2*2 + t];
        out[g*2 + t] = a;
    }
}

// ---------------- host launch ----------------
extern "C" void kernel_launch(void* const* d_in, const int* in_sizes, int n_in,
                              void* d_out, int out_size) {
    (void)in_sizes; (void)n_in; (void)out_size;
    const int*   x     = (const int*)d_in[0];
    const int*   ei    = (const int*)d_in[1];
    const float* emb   = (const float*)d_in[3];
    const float* gW1   = (const float*)d_in[4];
    const float* gb1v  = (const float*)d_in[5];
    const float* gW2   = (const float*)d_in[6];
    const float* gb2v  = (const float*)d_in[7];
    const float* bng   = (const float*)d_in[8];
    const float* bnb   = (const float*)d_in[9];
    const float* pW1   = (const float*)d_in[10];
    const float* pb1   = (const float*)d_in[11];
    const float* pW2   = (const float*)d_in[12];
    const float* pb2   = (const float*)d_in[13];
    const float* Wq    = (const float*)d_in[14];
    const float* Wk    = (const float*)d_in[15];
    const float* Wv    = (const float*)d_in[16];
    const float* Wo    = (const float*)d_in[17];
    const float* gateW1= (const float*)d_in[18];
    const float* gateb1= (const float*)d_in[19];
    const float* gateW2= (const float*)d_in[20];
    const float* gateb2= (const float*)d_in[21];
    const float* cbk   = (const float*)d_in[22];
    const float* cW1   = (const float*)d_in[23];
    const float* cb1   = (const float*)d_in[24];
    const float* cW2   = (const float*)d_in[25];
    const float* cb2   = (const float*)d_in[26];
    const float* cW3   = (const float*)d_in[27];
    const float* cb3   = (const float*)d_in[28];
    float* out = (float*)d_out;

    bf16 *w1hi, *w1lo, *w2hi, *w2lo, *pwhi, *pwlo;
    float *ppb1;
    cudaGetSymbolAddress((void**)&w1hi, g_w1hi);
    cudaGetSymbolAddress((void**)&w1lo, g_w1lo);
    cudaGetSymbolAddress((void**)&w2hi, g_w2hi);
    cudaGetSymbolAddress((void**)&w2lo, g_w2lo);
    cudaGetSymbolAddress((void**)&pwhi, g_pwhi);
    cudaGetSymbolAddress((void**)&pwlo, g_pwlo);
    cudaGetSymbolAddress((void**)&ppb1, g_pb1);

    cudaFuncSetAttribute(ginlayer, cudaFuncAttributeMaxDynamicSharedMemorySize, GIN2_SMEM);

    csr_kernel<<<BB, 512>>>(ei);
    {
        int tot = NN*DD + 3*DD*H2D + 3*H2D*DD + DD*128 + 128;
        prep_embed<<<(tot + 255)/256, 256>>>(x, emb, gW1, gW2, pW1, pb1);
    }

    for (int l = 0; l < 3; l++) {
        ginlayer<<<NN/64, 512, GIN2_SMEM>>>(
            w1hi + (size_t)l*DD*H2D, w1lo + (size_t)l*DD*H2D,
            w2hi + (size_t)l*H2D*DD, w2lo + (size_t)l*H2D*DD,
            gb1v + l*H2D, gb2v + l*DD, bng + l*DD, bnb + l*DD,
            pwhi, pwlo, ppb1, pW2, pb2,
            (l == 2) ? 1 : 0);
    }

    finale_kernel<<<BB, 640>>>(cbk, Wq, Wk, Wv, Wo, gateW1, gateb1, gateW2, gateb2,
                               cW1, cb1, cW2, cb2, cW3, cb3, out);
}